// round 7
// baseline (speedup 1.0000x reference)
#include <cuda_runtime.h>
#include <math.h>
#include <stdint.h>

// ---------------- problem constants ----------------
#define NTOT  8192
#define BGR   128
#define NPER  64
#define EDIR  65536
#define EKEEP 32768
#define EU    256
#define FIN   5
#define H1D   256
#define H2D   512
#define ATT   1536
#define EPSV  1e-5f

// ---------------- scratch (device globals; no allocation allowed) ----------------
__device__ float g_w[EDIR];
__device__ float g_agg1[NTOT * FIN];
__device__ float g_h1[NTOT * H1D];
__device__ float g_agg2[NTOT * H1D];
__device__ float g_h2[NTOT * H2D];
__device__ int   g_esrc[EKEEP];
__device__ int   g_edst[EKEEP];
__device__ int   g_kidx[EKEEP];
__device__ float g_feat[(size_t)EKEEP * ATT];
__device__ float g_Wq[ATT * ATT];
__device__ float g_Wk[ATT * ATT];
__device__ float g_Wv[ATT * ATT];
__device__ float g_Wqk[ATT * ATT];
__device__ float g_Wvo[ATT * ATT];
__device__ float g_bq[ATT];
__device__ float g_bv[ATT];
__device__ float g_rvec[ATT];
__device__ float g_bvo[ATT];
__device__ float g_rv[EKEEP];
__device__ float g_G[(size_t)EKEEP * ATT];
__device__ float g_FVo[(size_t)EKEEP * ATT];
__device__ float g_P1[(size_t)NTOT * ATT];
__device__ float g_P3[(size_t)NTOT * ATT];
__device__ float g_Q1[(size_t)NTOT * ATT];
__device__ float g_Q3[(size_t)NTOT * ATT];
__device__ float g_S[(size_t)BGR * EU * EU];
__device__ float g_logits[EKEEP];

// ---------------- tf32 helpers ----------------
__device__ __forceinline__ uint32_t f2tf(float x) {
    uint32_t r;
    asm("cvt.rna.tf32.f32 %0, %1;" : "=r"(r) : "f"(x));
    return r;
}
__device__ __forceinline__ void tfsplit(float x, uint32_t& b, uint32_t& s) {
    b = f2tf(x);
    s = f2tf(x - __uint_as_float(b));
}

// ---------------- 3xTF32 tensor-core GEMM: 128x128x16 tiles ----------------
// C = alpha * A @ B (or A @ B^T) [+ C] [+ bias] [relu], batched via blockIdx.z.
// fp32-comparable precision: Ab*Bb + Ab*Bs + As*Bb.
// Requires: M%128==0, N%128==0, K%16==0, leading dims %4==0.
// __launch_bounds__(256, 2): cap regs at 128 so 2 CTAs co-reside per SM and
// cover each other's sync/convert stalls.
template<bool TB, bool ACC, bool RELU, bool HASB>
__global__ __launch_bounds__(256, 2) void tgemm(
    const float* __restrict__ A, const float* __restrict__ B,
    float* __restrict__ C, const float* __restrict__ bias,
    int M, int N, int K, int lda, int ldb, int ldc,
    long long sA, long long sB, long long sC, long long sBias, float alpha)
{
    __shared__ uint32_t AsB[128][20], AsS[128][20];
    __shared__ uint32_t BsB[16][136], BsS[16][136];

    const int t  = threadIdx.x;
    const int bx = blockIdx.x, by = blockIdx.y, bz = blockIdx.z;
    const int n0 = bx * 128;
    const float* Ab = A + (long long)bz * sA + (long long)(by * 128) * lda;
    const float* Bb = B + (long long)bz * sB;
    float* Cb = C + (long long)bz * sC + (long long)(by * 128) * ldc + n0;

    const int lane = t & 31, wid = t >> 5;
    const int grp = lane >> 2, qid = lane & 3;
    const int wm = (wid & 1) * 64;
    const int wn = (wid >> 1) * 32;

    float acc[4][4][4];
#pragma unroll
    for (int mi = 0; mi < 4; mi++)
#pragma unroll
        for (int nj = 0; nj < 4; nj++)
#pragma unroll
            for (int h = 0; h < 4; h++) acc[mi][nj][h] = 0.f;

    const int ar = t >> 2, ac = (t & 3) * 4;
    const int br = t >> 5, bc = (t & 31) * 4;
    const int tr = t >> 1, tk = (t & 1) * 8;

    float4 ra[2], rb[2];

    auto gload = [&](int k0) {
        ra[0] = *reinterpret_cast<const float4*>(Ab + (long long)ar * lda + k0 + ac);
        ra[1] = *reinterpret_cast<const float4*>(Ab + (long long)(ar + 64) * lda + k0 + ac);
        if (TB) {
            rb[0] = *reinterpret_cast<const float4*>(Bb + (long long)(n0 + tr) * ldb + k0 + tk);
            rb[1] = *reinterpret_cast<const float4*>(Bb + (long long)(n0 + tr) * ldb + k0 + tk + 4);
        } else {
            rb[0] = *reinterpret_cast<const float4*>(Bb + (long long)(k0 + br) * ldb + n0 + bc);
            rb[1] = *reinterpret_cast<const float4*>(Bb + (long long)(k0 + br + 8) * ldb + n0 + bc);
        }
    };

    auto sstore = [&]() {
#pragma unroll
        for (int i = 0; i < 2; i++) {
            uint4 vb, vs;
            tfsplit(ra[i].x, vb.x, vs.x); tfsplit(ra[i].y, vb.y, vs.y);
            tfsplit(ra[i].z, vb.z, vs.z); tfsplit(ra[i].w, vb.w, vs.w);
            *reinterpret_cast<uint4*>(&AsB[i * 64 + ar][ac]) = vb;
            *reinterpret_cast<uint4*>(&AsS[i * 64 + ar][ac]) = vs;
        }
        if (TB) {
#pragma unroll
            for (int i = 0; i < 2; i++) {
                const float v[4] = {rb[i].x, rb[i].y, rb[i].z, rb[i].w};
#pragma unroll
                for (int j = 0; j < 4; j++) {
                    uint32_t b, s; tfsplit(v[j], b, s);
                    BsB[tk + i * 4 + j][tr] = b;
                    BsS[tk + i * 4 + j][tr] = s;
                }
            }
        } else {
#pragma unroll
            for (int i = 0; i < 2; i++) {
                uint4 vb, vs;
                tfsplit(rb[i].x, vb.x, vs.x); tfsplit(rb[i].y, vb.y, vs.y);
                tfsplit(rb[i].z, vb.z, vs.z); tfsplit(rb[i].w, vb.w, vs.w);
                *reinterpret_cast<uint4*>(&BsB[br + i * 8][bc]) = vb;
                *reinterpret_cast<uint4*>(&BsS[br + i * 8][bc]) = vs;
            }
        }
    };

    gload(0);
    sstore();
    __syncthreads();

    const int nk = K / 16;
    for (int kc = 0; kc < nk; kc++) {
        if (kc + 1 < nk) gload((kc + 1) * 16);

#pragma unroll
        for (int ks = 0; ks < 2; ks++) {
            const int k0 = ks * 8;
            uint32_t aB[4][4], aS[4][4];
#pragma unroll
            for (int mi = 0; mi < 4; mi++) {
                int r0 = wm + mi * 16 + grp;
                aB[mi][0] = AsB[r0][k0 + qid];
                aB[mi][1] = AsB[r0 + 8][k0 + qid];
                aB[mi][2] = AsB[r0][k0 + qid + 4];
                aB[mi][3] = AsB[r0 + 8][k0 + qid + 4];
                aS[mi][0] = AsS[r0][k0 + qid];
                aS[mi][1] = AsS[r0 + 8][k0 + qid];
                aS[mi][2] = AsS[r0][k0 + qid + 4];
                aS[mi][3] = AsS[r0 + 8][k0 + qid + 4];
            }
#pragma unroll
            for (int nj = 0; nj < 4; nj++) {
                int c0 = wn + nj * 8 + grp;
                uint32_t b0B = BsB[k0 + qid][c0];
                uint32_t b1B = BsB[k0 + qid + 4][c0];
                uint32_t b0S = BsS[k0 + qid][c0];
                uint32_t b1S = BsS[k0 + qid + 4][c0];
#pragma unroll
                for (int mi = 0; mi < 4; mi++) {
                    asm volatile(
                        "mma.sync.aligned.m16n8k8.row.col.f32.tf32.tf32.f32 "
                        "{%0,%1,%2,%3},{%4,%5,%6,%7},{%8,%9},{%0,%1,%2,%3};"
                        : "+f"(acc[mi][nj][0]), "+f"(acc[mi][nj][1]),
                          "+f"(acc[mi][nj][2]), "+f"(acc[mi][nj][3])
                        : "r"(aB[mi][0]), "r"(aB[mi][1]), "r"(aB[mi][2]), "r"(aB[mi][3]),
                          "r"(b0S), "r"(b1S));
                    asm volatile(
                        "mma.sync.aligned.m16n8k8.row.col.f32.tf32.tf32.f32 "
                        "{%0,%1,%2,%3},{%4,%5,%6,%7},{%8,%9},{%0,%1,%2,%3};"
                        : "+f"(acc[mi][nj][0]), "+f"(acc[mi][nj][1]),
                          "+f"(acc[mi][nj][2]), "+f"(acc[mi][nj][3])
                        : "r"(aS[mi][0]), "r"(aS[mi][1]), "r"(aS[mi][2]), "r"(aS[mi][3]),
                          "r"(b0B), "r"(b1B));
                    asm volatile(
                        "mma.sync.aligned.m16n8k8.row.col.f32.tf32.tf32.f32 "
                        "{%0,%1,%2,%3},{%4,%5,%6,%7},{%8,%9},{%0,%1,%2,%3};"
                        : "+f"(acc[mi][nj][0]), "+f"(acc[mi][nj][1]),
                          "+f"(acc[mi][nj][2]), "+f"(acc[mi][nj][3])
                        : "r"(aB[mi][0]), "r"(aB[mi][1]), "r"(aB[mi][2]), "r"(aB[mi][3]),
                          "r"(b0B), "r"(b1B));
                }
            }
        }

        __syncthreads();
        if (kc + 1 < nk) {
            sstore();
            __syncthreads();
        }
    }

    // epilogue
#pragma unroll
    for (int mi = 0; mi < 4; mi++) {
#pragma unroll
        for (int nj = 0; nj < 4; nj++) {
            int row = wm + mi * 16 + grp;
            int col = wn + nj * 8 + qid * 2;
#pragma unroll
            for (int h = 0; h < 2; h++) {
                int r = row + h * 8;
                float v0 = acc[mi][nj][h * 2 + 0] * alpha;
                float v1 = acc[mi][nj][h * 2 + 1] * alpha;
                if (HASB) {
                    const float* bp = bias + (long long)bz * sBias + n0 + col;
                    v0 += bp[0]; v1 += bp[1];
                }
                float2* cp = reinterpret_cast<float2*>(Cb + (long long)r * ldc + col);
                if (ACC) { float2 c = *cp; v0 += c.x; v1 += c.y; }
                if (RELU) { v0 = fmaxf(v0, 0.f); v1 = fmaxf(v1, 0.f); }
                *cp = make_float2(v0, v1);
            }
        }
    }
}

// ---------------- small kernels ----------------
__global__ void k_zero(float* p, int n) {
    int i = blockIdx.x * 256 + threadIdx.x;
    if (i < n) p[i] = 0.f;
}

__global__ void k_edgew(const float* __restrict__ ea, const float* __restrict__ W,
                        const float* __restrict__ b) {
    int e = blockIdx.x * 256 + threadIdx.x;
    if (e < EDIR) {
        float a = ea[2 * e], c = ea[2 * e + 1];
        float v = a * W[0] + ((c < 0.5f) ? W[1] : W[2]) + b[0];
        g_w[e] = fmaxf(v, 0.f);
    }
}

__global__ void k_sc1(const int* __restrict__ edges, const float* __restrict__ x) {
    int e = blockIdx.x * 256 + threadIdx.x;
    if (e < EDIR) {
        int s = edges[e], d = edges[EDIR + e];
        float wv = g_w[e];
        if (wv != 0.f) {
#pragma unroll
            for (int f = 0; f < FIN; f++)
                atomicAdd(&g_agg1[d * FIN + f], wv * x[s * FIN + f]);
        }
    }
}

__global__ void k_gc1(const float* __restrict__ x, const float* __restrict__ Wrel,
                      const float* __restrict__ brel, const float* __restrict__ Wroot) {
    int idx = blockIdx.x * 256 + threadIdx.x;
    int n = idx >> 8, j = idx & 255;
    float s = brel[j];
#pragma unroll
    for (int f = 0; f < FIN; f++) {
        s += g_agg1[n * FIN + f] * Wrel[f * H1D + j];
        s += x[n * FIN + f] * Wroot[f * H1D + j];
    }
    g_h1[idx] = fmaxf(s, 0.f);
}

__global__ void k_sc2(const int* __restrict__ edges) {
    int e = blockIdx.x;
    int t = threadIdx.x;
    int s = edges[e], d = edges[EDIR + e];
    float wv = g_w[e];
    if (wv == 0.f) return;
    float4 hv = *reinterpret_cast<const float4*>(&g_h1[s * H1D + t * 4]);
    atomicAdd(&g_agg2[d * H1D + t * 4 + 0], wv * hv.x);
    atomicAdd(&g_agg2[d * H1D + t * 4 + 1], wv * hv.y);
    atomicAdd(&g_agg2[d * H1D + t * 4 + 2], wv * hv.z);
    atomicAdd(&g_agg2[d * H1D + t * 4 + 3], wv * hv.w);
}

__global__ void k_gnorm(const float* __restrict__ gw, const float* __restrict__ gb,
                        const float* __restrict__ gms) {
    int g = blockIdx.x, j = threadIdx.x;
    float s = 0.f;
    for (int n = 0; n < NPER; n++) s += g_h2[((g << 6) + n) * H2D + j];
    float mean = s * (1.f / NPER);
    float ms = gms[j];
    float off = ms * mean;
    float s2 = 0.f;
    for (int n = 0; n < NPER; n++) {
        float c = g_h2[((g << 6) + n) * H2D + j] - off;
        s2 += c * c;
    }
    float inv = rsqrtf(s2 * (1.f / NPER) + EPSV);
    float wv = gw[j], bv = gb[j];
    for (int n = 0; n < NPER; n++) {
        int idx = ((g << 6) + n) * H2D + j;
        g_h2[idx] = wv * (g_h2[idx] - off) * inv + bv;
    }
}

__global__ void k_sort(const int* __restrict__ edges) {
    __shared__ unsigned int key[256];
    int g = blockIdx.x, t = threadIdx.x;
    int ge = g * 512 + 256 + t;
    int s = edges[ge], d = edges[EDIR + ge];
    unsigned int k = ((unsigned)((s - (g << 6)) * 64 + (d - (g << 6))) << 8) | (unsigned)t;
    key[t] = k;
    __syncthreads();
    for (int kk = 2; kk <= 256; kk <<= 1) {
        for (int j = kk >> 1; j > 0; j >>= 1) {
            int ixj = t ^ j;
            if (ixj > t) {
                unsigned a = key[t], b = key[ixj];
                bool up = (t & kk) == 0;
                if ((a > b) == up) { key[t] = b; key[ixj] = a; }
            }
            __syncthreads();
        }
    }
    int slot = key[t] & 255;
    int ge2 = g * 512 + 256 + slot;
    int i = g * 256 + t;
    g_esrc[i] = edges[ge2];
    g_edst[i] = edges[EDIR + ge2];
    g_kidx[i] = ge2;
}

__global__ void k_feat(const float* __restrict__ ea, const float* __restrict__ eW,
                       const float* __restrict__ eb) {
    int i = blockIdx.x, t = threadIdx.x;
    int s = g_esrc[i], d = g_edst[i], ke = g_kidx[i];
    float a = ea[2 * ke], c = ea[2 * ke + 1];
    float* F = g_feat + (long long)i * ATT;
    for (int j = t; j < H2D; j += 256) {
        F[j]        = g_h2[s * H2D + j];
        F[1024 + j] = g_h2[d * H2D + j];
        float e = a * eW[j] + ((c < 0.5f) ? eW[512 + j] : eW[1024 + j]) + eb[j];
        F[512 + j] = fmaxf(e, 0.f);
    }
}

// G[i] += P1[src_i] + P3[dst_i];  FVo[i] += Q1[src_i] + Q3[dst_i]
__global__ void k_gadd() {
    int i = blockIdx.x, t = threadIdx.x;
    int s = g_esrc[i], d = g_edst[i];
    const float4* p1 = reinterpret_cast<const float4*>(g_P1 + (long long)s * ATT);
    const float4* p3 = reinterpret_cast<const float4*>(g_P3 + (long long)d * ATT);
    const float4* q1 = reinterpret_cast<const float4*>(g_Q1 + (long long)s * ATT);
    const float4* q3 = reinterpret_cast<const float4*>(g_Q3 + (long long)d * ATT);
    float4* gr = reinterpret_cast<float4*>(g_G + (long long)i * ATT);
    float4* fr = reinterpret_cast<float4*>(g_FVo + (long long)i * ATT);
#pragma unroll
    for (int jj = 0; jj < 2; jj++) {
        int j = t + jj * 256;
        if (j < ATT / 4) {
            float4 g = gr[j], a = p1[j], b = p3[j];
            g.x += a.x + b.x; g.y += a.y + b.y; g.z += a.z + b.z; g.w += a.w + b.w;
            gr[j] = g;
            float4 f = fr[j], c = q1[j], e = q3[j];
            f.x += c.x + e.x; f.y += c.y + e.y; f.z += c.z + e.z; f.w += c.w + e.w;
            fr[j] = f;
        }
    }
}

__global__ void k_vecmat(const float* __restrict__ x, const float* __restrict__ W,
                         const float* __restrict__ b, float* __restrict__ y,
                         int K, int N, int ldw) {
    int j = blockIdx.x * 256 + threadIdx.x;
    if (j < N) {
        float s = b ? b[j] : 0.f;
        for (int i = 0; i < K; i++) s += x[i] * W[(long long)i * ldw + j];
        y[j] = s;
    }
}

__global__ void k_matvecr(const float* __restrict__ W, const float* __restrict__ x,
                          float* __restrict__ y, float scale) {
    int row = blockIdx.x, t = threadIdx.x;
    float s = 0.f;
    for (int j = t; j < ATT; j += 256) s += W[(long long)row * ATT + j] * x[j];
    __shared__ float red[256];
    red[t] = s; __syncthreads();
    for (int st = 128; st > 0; st >>= 1) { if (t < st) red[t] += red[t + st]; __syncthreads(); }
    if (t == 0) y[row] = red[0] * scale;
}

__global__ void k_rowdot() {
    int row = blockIdx.x, t = threadIdx.x;
    const float* F = g_feat + (long long)row * ATT;
    float s = 0.f;
    for (int j = t; j < ATT; j += 256) s += F[j] * g_rvec[j];
    __shared__ float red[256];
    red[t] = s; __syncthreads();
    for (int st = 128; st > 0; st >>= 1) { if (t < st) red[t] += red[t + st]; __syncthreads(); }
    if (t == 0) g_rv[row] = red[0];
}

__global__ void k_softmax() {
    int rb = blockIdx.x, t = threadIdx.x;
    float v = g_S[(long long)rb * 256 + t];
    __shared__ float red[256];
    red[t] = v; __syncthreads();
    for (int s = 128; s > 0; s >>= 1) { if (t < s) red[t] = fmaxf(red[t], red[t + s]); __syncthreads(); }
    float m = red[0]; __syncthreads();
    float e = __expf(v - m);
    red[t] = e; __syncthreads();
    for (int s = 128; s > 0; s >>= 1) { if (t < s) red[t] += red[t + s]; __syncthreads(); }
    g_S[(long long)rb * 256 + t] = e / red[0];
}

__global__ void k_ln_head(const float* __restrict__ lng, const float* __restrict__ lnb,
                          const float* __restrict__ hW, const float* __restrict__ hb) {
    int row = blockIdx.x, t = threadIdx.x;
    const float* x = g_feat + (long long)row * ATT;
    float loc[6];
    float s = 0.f;
#pragma unroll
    for (int i = 0; i < 6; i++) { loc[i] = x[t + i * 256]; s += loc[i]; }
    __shared__ float red[256];
    red[t] = s; __syncthreads();
    for (int st = 128; st > 0; st >>= 1) { if (t < st) red[t] += red[t + st]; __syncthreads(); }
    float mu = red[0] * (1.f / ATT); __syncthreads();
    float s2 = 0.f;
#pragma unroll
    for (int i = 0; i < 6; i++) { float d = loc[i] - mu; s2 += d * d; }
    red[t] = s2; __syncthreads();
    for (int st = 128; st > 0; st >>= 1) { if (t < st) red[t] += red[t + st]; __syncthreads(); }
    float inv = rsqrtf(red[0] * (1.f / ATT) + EPSV); __syncthreads();
    float o = 0.f;
#pragma unroll
    for (int i = 0; i < 6; i++) {
        int j = t + i * 256;
        float nv = lng[j] * (loc[i] - mu) * inv + lnb[j];
        o += nv * hW[j];
    }
    red[t] = o; __syncthreads();
    for (int st = 128; st > 0; st >>= 1) { if (t < st) red[t] += red[t + st]; __syncthreads(); }
    if (t == 0) g_logits[row] = red[0] + hb[0];
}

__global__ void k_final(const float* __restrict__ ea, float* __restrict__ out) {
    int idx = blockIdx.x * 256 + threadIdx.x;
    if (idx < BGR * 128) {
        int i0 = 2 * idx, i1 = i0 + 1;
        float v0 = g_logits[i0], v1 = g_logits[i1];
        float c0 = ea[2 * g_kidx[i0] + 1], c1 = ea[2 * g_kidx[i1] + 1];
        int m = (v1 < v0) ? 1 : 0;
        out[idx * 2 + 0] = (float)g_esrc[i0];
        out[idx * 2 + 1] = (float)g_edst[i0];
        out[32768 + idx] = m ? v1 : v0;
        out[49152 + idx] = m ? c1 : c0;
    }
}

// ---------------- host-side GEMM dispatch ----------------
template<bool TB, bool ACC, bool RELU, bool HASB>
static void gemm(const float* A, const float* B, float* C, const float* bias,
                 int M, int N, int K, int lda, int ldb, int ldc,
                 long long sA, long long sB, long long sC, long long sBias,
                 float alpha, int batch) {
    dim3 grid(N / 128, M / 128, batch);
    tgemm<TB, ACC, RELU, HASB><<<grid, 256>>>(A, B, C, bias, M, N, K, lda, ldb, ldc,
                                              sA, sB, sC, sBias, alpha);
}

static float* sym(const void* s) {
    void* p = nullptr;
    cudaGetSymbolAddress(&p, s);
    return (float*)p;
}

extern "C" void kernel_launch(void* const* d_in, const int* in_sizes, int n_in,
                              void* d_out, int out_size) {
    const float* x       = (const float*)d_in[0];
    const int*   edges   = (const int*)d_in[1];
    const float* ea      = (const float*)d_in[2];
    const float* wembW   = (const float*)d_in[5];
    const float* wembB   = (const float*)d_in[6];
    const float* gc1Wrel = (const float*)d_in[7];
    const float* gc1brel = (const float*)d_in[8];
    const float* gc1Wroot= (const float*)d_in[9];
    const float* gc2Wrel = (const float*)d_in[10];
    const float* gc2brel = (const float*)d_in[11];
    const float* gc2Wroot= (const float*)d_in[12];
    const float* gnw     = (const float*)d_in[13];
    const float* gnb     = (const float*)d_in[14];
    const float* gnms    = (const float*)d_in[15];
    const float* eW      = (const float*)d_in[16];
    const float* ebias   = (const float*)d_in[17];
    const float* qkvW    = (const float*)d_in[18];
    const float* qkvb    = (const float*)d_in[19];
    const float* inWq    = (const float*)d_in[20];
    const float* inWk    = (const float*)d_in[21];
    const float* inWv    = (const float*)d_in[22];
    const float* inbq    = (const float*)d_in[23];
    const float* inbv    = (const float*)d_in[25];
    const float* outW    = (const float*)d_in[26];
    const float* outb    = (const float*)d_in[27];
    const float* lng     = (const float*)d_in[28];
    const float* lnb     = (const float*)d_in[29];
    const float* hW      = (const float*)d_in[30];
    const float* hb      = (const float*)d_in[31];
    (void)in_sizes; (void)n_in; (void)out_size;

    float* agg1 = sym(g_agg1);  float* agg2 = sym(g_agg2);
    float* h1   = sym(g_h1);    float* h2   = sym(g_h2);
    float* feat = sym(g_feat);
    float* Wq   = sym(g_Wq);    float* Wk  = sym(g_Wk);   float* Wv  = sym(g_Wv);
    float* Wqk  = sym(g_Wqk);   float* Wvo = sym(g_Wvo);
    float* bq   = sym(g_bq);    float* bv  = sym(g_bv);
    float* rvec = sym(g_rvec);  float* bvo = sym(g_bvo);  float* rv  = sym(g_rv);
    float* G    = sym(g_G);     float* FVo = sym(g_FVo);  float* S   = sym(g_S);
    float* P1   = sym(g_P1);    float* P3  = sym(g_P3);
    float* Q1   = sym(g_Q1);    float* Q3  = sym(g_Q3);

    const float scale = 1.0f / sqrtf((float)ATT);

    // deterministic launch ordering: index 5 (ncu -s 5 -c 1) = tgemm (Wq fold)
    k_zero<<<(NTOT * FIN + 255) / 256, 256>>>(agg1, NTOT * FIN);          // 0
    k_zero<<<(NTOT * H1D + 255) / 256, 256>>>(agg2, NTOT * H1D);          // 1
    k_edgew<<<EDIR / 256, 256>>>(ea, wembW, wembB);                        // 2
    k_sc1<<<EDIR / 256, 256>>>(edges, x);                                  // 3
    k_gc1<<<NTOT * H1D / 256, 256>>>(x, gc1Wrel, gc1brel, gc1Wroot);       // 4
    // 5 — profiled: Wq fold (representative tgemm, K=1536)
    gemm<false, false, false, false>(qkvW + 0, inWq, Wq, nullptr,
                                     ATT, ATT, ATT, 3 * ATT, ATT, ATT, 0, 0, 0, 0, 1.f, 1);
    k_sc2<<<EDIR, 64>>>(edges);
    gemm<false, false, false, false>(agg2, gc2Wrel, h2, nullptr,
                                     NTOT, H2D, H1D, H1D, H2D, H2D, 0, 0, 0, 0, 1.f, 1);
    gemm<false, true, true, true>(h1, gc2Wroot, h2, gc2brel,
                                  NTOT, H2D, H1D, H1D, H2D, H2D, 0, 0, 0, 0, 1.f, 1);
    k_gnorm<<<BGR, H2D>>>(gnw, gnb, gnms);
    k_sort<<<BGR, 256>>>(edges);
    k_feat<<<EKEEP, 256>>>(ea, eW, ebias);

    // ---- remaining weight folds ----
    gemm<false, false, false, false>(qkvW + ATT,  inWk, Wk, nullptr, ATT, ATT, ATT, 3 * ATT, ATT, ATT, 0, 0, 0, 0, 1.f, 1);
    gemm<false, false, false, false>(qkvW + 2*ATT,inWv, Wv, nullptr, ATT, ATT, ATT, 3 * ATT, ATT, ATT, 0, 0, 0, 0, 1.f, 1);
    k_vecmat<<<ATT / 256, 256>>>(qkvb + 0,     inWq, inbq, bq, ATT, ATT, ATT);
    k_vecmat<<<ATT / 256, 256>>>(qkvb + 2*ATT, inWv, inbv, bv, ATT, ATT, ATT);
    k_matvecr<<<ATT, 256>>>(Wk, bq, rvec, scale);           // r = scale * Wk_eff @ bq_eff
    k_vecmat<<<ATT / 256, 256>>>(bv, outW, outb, bvo, ATT, ATT, ATT);
    gemm<true,  false, false, false>(Wq, Wk, Wqk, nullptr, ATT, ATT, ATT, ATT, ATT, ATT, 0, 0, 0, 0, scale, 1);
    gemm<false, false, false, false>(Wv, outW, Wvo, nullptr, ATT, ATT, ATT, ATT, ATT, ATT, 0, 0, 0, 0, 1.f, 1);

    // ---- decomposed projections: G = P1[src] + emb@Wqk_mid + P3[dst] ----
    gemm<false, false, false, false>(feat + 512, Wqk + (long long)512 * ATT, G, nullptr,
                                     EKEEP, ATT, 512, ATT, ATT, ATT, 0, 0, 0, 0, 1.f, 1);
    gemm<false, false, false, true>(feat + 512, Wvo + (long long)512 * ATT, FVo, bvo,
                                    EKEEP, ATT, 512, ATT, ATT, ATT, 0, 0, 0, 0, 1.f, 1);
    gemm<false, false, false, false>(h2, Wqk, P1, nullptr,
                                     NTOT, ATT, 512, H2D, ATT, ATT, 0, 0, 0, 0, 1.f, 1);
    gemm<false, false, false, false>(h2, Wqk + (long long)1024 * ATT, P3, nullptr,
                                     NTOT, ATT, 512, H2D, ATT, ATT, 0, 0, 0, 0, 1.f, 1);
    gemm<false, false, false, false>(h2, Wvo, Q1, nullptr,
                                     NTOT, ATT, 512, H2D, ATT, ATT, 0, 0, 0, 0, 1.f, 1);
    gemm<false, false, false, false>(h2, Wvo + (long long)1024 * ATT, Q3, nullptr,
                                     NTOT, ATT, 512, H2D, ATT, ATT, 0, 0, 0, 0, 1.f, 1);
    k_gadd<<<EKEEP, 256>>>();

    // ---- attention ----
    k_rowdot<<<EKEEP, 256>>>();                             // rv = feat @ rvec
    gemm<true, false, false, true>(G, feat, S, rv,
                                   EU, EU, ATT, ATT, ATT, EU,
                                   (long long)EU * ATT, (long long)EU * ATT,
                                   (long long)EU * EU, EU, 1.f, BGR);
    k_softmax<<<EKEEP, 256>>>();
    gemm<false, true, false, false>(S, FVo, feat, nullptr,
                                    EU, ATT, EU, EU, ATT, ATT,
                                    (long long)EU * EU, (long long)EU * ATT,
                                    (long long)EU * ATT, 0, 1.f, BGR);

    // ---- LN + head + pairing ----
    k_ln_head<<<EKEEP, 256>>>(lng, lnb, hW, hb);
    k_final<<<(BGR * 128) / 256, 256>>>(ea, (float*)d_out);
}

// round 8
// speedup vs baseline: 1.3928x; 1.3928x over previous
#include <cuda_runtime.h>
#include <math.h>
#include <stdint.h>

// ---------------- problem constants ----------------
#define NTOT  8192
#define BGR   128
#define NPER  64
#define EDIR  65536
#define EKEEP 32768
#define EU    256
#define FIN   5
#define H1D   256
#define H2D   512
#define ATT   1536
#define EPSV  1e-5f

// ---------------- scratch (device globals; no allocation allowed) ----------------
__device__ float g_w[EDIR];
__device__ float g_agg1[NTOT * FIN];
__device__ float g_h1[NTOT * H1D];
__device__ float g_agg2[NTOT * H1D];
__device__ float g_h2[NTOT * H2D];
__device__ int   g_esrc[EKEEP];
__device__ int   g_edst[EKEEP];
__device__ int   g_kidx[EKEEP];
__device__ float g_feat[(size_t)EKEEP * ATT];
__device__ float g_Wq[ATT * ATT];
__device__ float g_Wk[ATT * ATT];
__device__ float g_Wv[ATT * ATT];
__device__ float g_Wqk[ATT * ATT];
__device__ float g_Wvo[ATT * ATT];
__device__ float g_bq[ATT];
__device__ float g_bv[ATT];
__device__ float g_rvec[ATT];
__device__ float g_bvo[ATT];
__device__ float g_rv[EKEEP];
__device__ float g_G[(size_t)EKEEP * ATT];
__device__ float g_FVo[(size_t)EKEEP * ATT];
__device__ float g_P1[(size_t)NTOT * ATT];
__device__ float g_P3[(size_t)NTOT * ATT];
__device__ float g_Q1[(size_t)NTOT * ATT];
__device__ float g_Q3[(size_t)NTOT * ATT];
__device__ float g_S[(size_t)BGR * EU * EU];
__device__ float g_logits[EKEEP];

// ---------------- tf32 helpers ----------------
__device__ __forceinline__ uint32_t f2tf(float x) {
    uint32_t r;
    asm("cvt.rna.tf32.f32 %0, %1;" : "=r"(r) : "f"(x));
    return r;
}
__device__ __forceinline__ void tfsplit(float x, uint32_t& b, uint32_t& s) {
    b = f2tf(x);
    s = f2tf(x - __uint_as_float(b));
}

// ---------------- 3xTF32 tensor-core GEMM: 128x128x16 tiles (round-4 proven) ----
// C = alpha * A @ B (or A @ B^T) [+ C] [+ bias] [relu] [+ gathered tables], batched.
// fp32-comparable precision: Ab*Bb + Ab*Bs + As*Bb.
// GAT: C[row] += T1[g_esrc[row]*ATT + col] + T2[g_edst[row]*ATT + col]  (bz==0 use).
template<bool TB, bool ACC, bool RELU, bool HASB, bool GAT>
__global__ __launch_bounds__(256) void tgemm(
    const float* __restrict__ A, const float* __restrict__ B,
    float* __restrict__ C, const float* __restrict__ bias,
    int M, int N, int K, int lda, int ldb, int ldc,
    long long sA, long long sB, long long sC, long long sBias, float alpha,
    const float* __restrict__ T1, const float* __restrict__ T2)
{
    __shared__ uint32_t AsB[128][20], AsS[128][20];
    __shared__ uint32_t BsB[16][136], BsS[16][136];

    const int t  = threadIdx.x;
    const int bx = blockIdx.x, by = blockIdx.y, bz = blockIdx.z;
    const int n0 = bx * 128;
    const float* Ab = A + (long long)bz * sA + (long long)(by * 128) * lda;
    const float* Bb = B + (long long)bz * sB;
    float* Cb = C + (long long)bz * sC + (long long)(by * 128) * ldc + n0;

    const int lane = t & 31, wid = t >> 5;
    const int grp = lane >> 2, qid = lane & 3;
    const int wm = (wid & 1) * 64;
    const int wn = (wid >> 1) * 32;

    float acc[4][4][4];
#pragma unroll
    for (int mi = 0; mi < 4; mi++)
#pragma unroll
        for (int nj = 0; nj < 4; nj++)
#pragma unroll
            for (int h = 0; h < 4; h++) acc[mi][nj][h] = 0.f;

    const int ar = t >> 2, ac = (t & 3) * 4;
    const int br = t >> 5, bc = (t & 31) * 4;
    const int tr = t >> 1, tk = (t & 1) * 8;

    float4 ra[2], rb[2];

    auto gload = [&](int k0) {
        ra[0] = *reinterpret_cast<const float4*>(Ab + (long long)ar * lda + k0 + ac);
        ra[1] = *reinterpret_cast<const float4*>(Ab + (long long)(ar + 64) * lda + k0 + ac);
        if (TB) {
            rb[0] = *reinterpret_cast<const float4*>(Bb + (long long)(n0 + tr) * ldb + k0 + tk);
            rb[1] = *reinterpret_cast<const float4*>(Bb + (long long)(n0 + tr) * ldb + k0 + tk + 4);
        } else {
            rb[0] = *reinterpret_cast<const float4*>(Bb + (long long)(k0 + br) * ldb + n0 + bc);
            rb[1] = *reinterpret_cast<const float4*>(Bb + (long long)(k0 + br + 8) * ldb + n0 + bc);
        }
    };

    auto sstore = [&]() {
#pragma unroll
        for (int i = 0; i < 2; i++) {
            uint4 vb, vs;
            tfsplit(ra[i].x, vb.x, vs.x); tfsplit(ra[i].y, vb.y, vs.y);
            tfsplit(ra[i].z, vb.z, vs.z); tfsplit(ra[i].w, vb.w, vs.w);
            *reinterpret_cast<uint4*>(&AsB[i * 64 + ar][ac]) = vb;
            *reinterpret_cast<uint4*>(&AsS[i * 64 + ar][ac]) = vs;
        }
        if (TB) {
#pragma unroll
            for (int i = 0; i < 2; i++) {
                const float v[4] = {rb[i].x, rb[i].y, rb[i].z, rb[i].w};
#pragma unroll
                for (int j = 0; j < 4; j++) {
                    uint32_t b, s; tfsplit(v[j], b, s);
                    BsB[tk + i * 4 + j][tr] = b;
                    BsS[tk + i * 4 + j][tr] = s;
                }
            }
        } else {
#pragma unroll
            for (int i = 0; i < 2; i++) {
                uint4 vb, vs;
                tfsplit(rb[i].x, vb.x, vs.x); tfsplit(rb[i].y, vb.y, vs.y);
                tfsplit(rb[i].z, vb.z, vs.z); tfsplit(rb[i].w, vb.w, vs.w);
                *reinterpret_cast<uint4*>(&BsB[br + i * 8][bc]) = vb;
                *reinterpret_cast<uint4*>(&BsS[br + i * 8][bc]) = vs;
            }
        }
    };

    gload(0);
    sstore();
    __syncthreads();

    const int nk = K / 16;
    for (int kc = 0; kc < nk; kc++) {
        if (kc + 1 < nk) gload((kc + 1) * 16);

#pragma unroll
        for (int ks = 0; ks < 2; ks++) {
            const int k0 = ks * 8;
            uint32_t aB[4][4], aS[4][4];
#pragma unroll
            for (int mi = 0; mi < 4; mi++) {
                int r0 = wm + mi * 16 + grp;
                aB[mi][0] = AsB[r0][k0 + qid];
                aB[mi][1] = AsB[r0 + 8][k0 + qid];
                aB[mi][2] = AsB[r0][k0 + qid + 4];
                aB[mi][3] = AsB[r0 + 8][k0 + qid + 4];
                aS[mi][0] = AsS[r0][k0 + qid];
                aS[mi][1] = AsS[r0 + 8][k0 + qid];
                aS[mi][2] = AsS[r0][k0 + qid + 4];
                aS[mi][3] = AsS[r0 + 8][k0 + qid + 4];
            }
#pragma unroll
            for (int nj = 0; nj < 4; nj++) {
                int c0 = wn + nj * 8 + grp;
                uint32_t b0B = BsB[k0 + qid][c0];
                uint32_t b1B = BsB[k0 + qid + 4][c0];
                uint32_t b0S = BsS[k0 + qid][c0];
                uint32_t b1S = BsS[k0 + qid + 4][c0];
#pragma unroll
                for (int mi = 0; mi < 4; mi++) {
                    asm volatile(
                        "mma.sync.aligned.m16n8k8.row.col.f32.tf32.tf32.f32 "
                        "{%0,%1,%2,%3},{%4,%5,%6,%7},{%8,%9},{%0,%1,%2,%3};"
                        : "+f"(acc[mi][nj][0]), "+f"(acc[mi][nj][1]),
                          "+f"(acc[mi][nj][2]), "+f"(acc[mi][nj][3])
                        : "r"(aB[mi][0]), "r"(aB[mi][1]), "r"(aB[mi][2]), "r"(aB[mi][3]),
                          "r"(b0S), "r"(b1S));
                    asm volatile(
                        "mma.sync.aligned.m16n8k8.row.col.f32.tf32.tf32.f32 "
                        "{%0,%1,%2,%3},{%4,%5,%6,%7},{%8,%9},{%0,%1,%2,%3};"
                        : "+f"(acc[mi][nj][0]), "+f"(acc[mi][nj][1]),
                          "+f"(acc[mi][nj][2]), "+f"(acc[mi][nj][3])
                        : "r"(aS[mi][0]), "r"(aS[mi][1]), "r"(aS[mi][2]), "r"(aS[mi][3]),
                          "r"(b0B), "r"(b1B));
                    asm volatile(
                        "mma.sync.aligned.m16n8k8.row.col.f32.tf32.tf32.f32 "
                        "{%0,%1,%2,%3},{%4,%5,%6,%7},{%8,%9},{%0,%1,%2,%3};"
                        : "+f"(acc[mi][nj][0]), "+f"(acc[mi][nj][1]),
                          "+f"(acc[mi][nj][2]), "+f"(acc[mi][nj][3])
                        : "r"(aB[mi][0]), "r"(aB[mi][1]), "r"(aB[mi][2]), "r"(aB[mi][3]),
                          "r"(b0B), "r"(b1B));
                }
            }
        }

        __syncthreads();
        if (kc + 1 < nk) {
            sstore();
            __syncthreads();
        }
    }

    // epilogue
#pragma unroll
    for (int mi = 0; mi < 4; mi++) {
#pragma unroll
        for (int nj = 0; nj < 4; nj++) {
            int row = wm + mi * 16 + grp;
            int col = wn + nj * 8 + qid * 2;
#pragma unroll
            for (int h = 0; h < 2; h++) {
                int r = row + h * 8;
                float v0 = acc[mi][nj][h * 2 + 0] * alpha;
                float v1 = acc[mi][nj][h * 2 + 1] * alpha;
                if (HASB) {
                    const float* bp = bias + (long long)bz * sBias + n0 + col;
                    v0 += bp[0]; v1 += bp[1];
                }
                if (GAT) {
                    int e = by * 128 + r;
                    int es = g_esrc[e], ed = g_edst[e];
                    float2 t1 = *reinterpret_cast<const float2*>(&T1[(long long)es * ATT + n0 + col]);
                    float2 t2 = *reinterpret_cast<const float2*>(&T2[(long long)ed * ATT + n0 + col]);
                    v0 += t1.x + t2.x; v1 += t1.y + t2.y;
                }
                float2* cp = reinterpret_cast<float2*>(Cb + (long long)r * ldc + col);
                if (ACC) { float2 c = *cp; v0 += c.x; v1 += c.y; }
                if (RELU) { v0 = fmaxf(v0, 0.f); v1 = fmaxf(v1, 0.f); }
                *cp = make_float2(v0, v1);
            }
        }
    }
}

// ---------------- small kernels ----------------
__global__ void k_zero(float* p, int n) {
    int i = blockIdx.x * 256 + threadIdx.x;
    if (i < n) p[i] = 0.f;
}

__global__ void k_edgew(const float* __restrict__ ea, const float* __restrict__ W,
                        const float* __restrict__ b) {
    int e = blockIdx.x * 256 + threadIdx.x;
    if (e < EDIR) {
        float a = ea[2 * e], c = ea[2 * e + 1];
        float v = a * W[0] + ((c < 0.5f) ? W[1] : W[2]) + b[0];
        g_w[e] = fmaxf(v, 0.f);
    }
}

__global__ void k_sc1(const int* __restrict__ edges, const float* __restrict__ x) {
    int e = blockIdx.x * 256 + threadIdx.x;
    if (e < EDIR) {
        int s = edges[e], d = edges[EDIR + e];
        float wv = g_w[e];
        if (wv != 0.f) {
#pragma unroll
            for (int f = 0; f < FIN; f++)
                atomicAdd(&g_agg1[d * FIN + f], wv * x[s * FIN + f]);
        }
    }
}

__global__ void k_gc1(const float* __restrict__ x, const float* __restrict__ Wrel,
                      const float* __restrict__ brel, const float* __restrict__ Wroot) {
    int idx = blockIdx.x * 256 + threadIdx.x;
    int n = idx >> 8, j = idx & 255;
    float s = brel[j];
#pragma unroll
    for (int f = 0; f < FIN; f++) {
        s += g_agg1[n * FIN + f] * Wrel[f * H1D + j];
        s += x[n * FIN + f] * Wroot[f * H1D + j];
    }
    g_h1[idx] = fmaxf(s, 0.f);
}

__global__ void k_sc2(const int* __restrict__ edges) {
    int e = blockIdx.x;
    int t = threadIdx.x;
    int s = edges[e], d = edges[EDIR + e];
    float wv = g_w[e];
    if (wv == 0.f) return;
    float4 hv = *reinterpret_cast<const float4*>(&g_h1[s * H1D + t * 4]);
    atomicAdd(&g_agg2[d * H1D + t * 4 + 0], wv * hv.x);
    atomicAdd(&g_agg2[d * H1D + t * 4 + 1], wv * hv.y);
    atomicAdd(&g_agg2[d * H1D + t * 4 + 2], wv * hv.z);
    atomicAdd(&g_agg2[d * H1D + t * 4 + 3], wv * hv.w);
}

__global__ void k_gnorm(const float* __restrict__ gw, const float* __restrict__ gb,
                        const float* __restrict__ gms) {
    int g = blockIdx.x, j = threadIdx.x;
    float s = 0.f;
    for (int n = 0; n < NPER; n++) s += g_h2[((g << 6) + n) * H2D + j];
    float mean = s * (1.f / NPER);
    float ms = gms[j];
    float off = ms * mean;
    float s2 = 0.f;
    for (int n = 0; n < NPER; n++) {
        float c = g_h2[((g << 6) + n) * H2D + j] - off;
        s2 += c * c;
    }
    float inv = rsqrtf(s2 * (1.f / NPER) + EPSV);
    float wv = gw[j], bv = gb[j];
    for (int n = 0; n < NPER; n++) {
        int idx = ((g << 6) + n) * H2D + j;
        g_h2[idx] = wv * (g_h2[idx] - off) * inv + bv;
    }
}

__global__ void k_sort(const int* __restrict__ edges) {
    __shared__ unsigned int key[256];
    int g = blockIdx.x, t = threadIdx.x;
    int ge = g * 512 + 256 + t;
    int s = edges[ge], d = edges[EDIR + ge];
    unsigned int k = ((unsigned)((s - (g << 6)) * 64 + (d - (g << 6))) << 8) | (unsigned)t;
    key[t] = k;
    __syncthreads();
    for (int kk = 2; kk <= 256; kk <<= 1) {
        for (int j = kk >> 1; j > 0; j >>= 1) {
            int ixj = t ^ j;
            if (ixj > t) {
                unsigned a = key[t], b = key[ixj];
                bool up = (t & kk) == 0;
                if ((a > b) == up) { key[t] = b; key[ixj] = a; }
            }
            __syncthreads();
        }
    }
    int slot = key[t] & 255;
    int ge2 = g * 512 + 256 + slot;
    int i = g * 256 + t;
    g_esrc[i] = edges[ge2];
    g_edst[i] = edges[EDIR + ge2];
    g_kidx[i] = ge2;
}

__global__ void k_feat(const float* __restrict__ ea, const float* __restrict__ eW,
                       const float* __restrict__ eb) {
    int i = blockIdx.x, t = threadIdx.x;
    int s = g_esrc[i], d = g_edst[i], ke = g_kidx[i];
    float a = ea[2 * ke], c = ea[2 * ke + 1];
    float* F = g_feat + (long long)i * ATT;
    for (int j = t; j < H2D; j += 256) {
        F[j]        = g_h2[s * H2D + j];
        F[1024 + j] = g_h2[d * H2D + j];
        float e = a * eW[j] + ((c < 0.5f) ? eW[512 + j] : eW[1024 + j]) + eb[j];
        F[512 + j] = fmaxf(e, 0.f);
    }
}

__global__ void k_vecmat(const float* __restrict__ x, const float* __restrict__ W,
                         const float* __restrict__ b, float* __restrict__ y,
                         int K, int N, int ldw) {
    int j = blockIdx.x * 256 + threadIdx.x;
    if (j < N) {
        float s = b ? b[j] : 0.f;
        for (int i = 0; i < K; i++) s += x[i] * W[(long long)i * ldw + j];
        y[j] = s;
    }
}

__global__ void k_matvecr(const float* __restrict__ W, const float* __restrict__ x,
                          float* __restrict__ y, float scale) {
    int row = blockIdx.x, t = threadIdx.x;
    float s = 0.f;
    for (int j = t; j < ATT; j += 256) s += W[(long long)row * ATT + j] * x[j];
    __shared__ float red[256];
    red[t] = s; __syncthreads();
    for (int st = 128; st > 0; st >>= 1) { if (t < st) red[t] += red[t + st]; __syncthreads(); }
    if (t == 0) y[row] = red[0] * scale;
}

__global__ void k_rowdot() {
    int row = blockIdx.x, t = threadIdx.x;
    const float* F = g_feat + (long long)row * ATT;
    float s = 0.f;
    for (int j = t; j < ATT; j += 256) s += F[j] * g_rvec[j];
    __shared__ float red[256];
    red[t] = s; __syncthreads();
    for (int st = 128; st > 0; st >>= 1) { if (t < st) red[t] += red[t + st]; __syncthreads(); }
    if (t == 0) g_rv[row] = red[0];
}

__global__ void k_softmax() {
    int rb = blockIdx.x, t = threadIdx.x;
    float v = g_S[(long long)rb * 256 + t];
    __shared__ float red[256];
    red[t] = v; __syncthreads();
    for (int s = 128; s > 0; s >>= 1) { if (t < s) red[t] = fmaxf(red[t], red[t + s]); __syncthreads(); }
    float m = red[0]; __syncthreads();
    float e = __expf(v - m);
    red[t] = e; __syncthreads();
    for (int s = 128; s > 0; s >>= 1) { if (t < s) red[t] += red[t + s]; __syncthreads(); }
    g_S[(long long)rb * 256 + t] = e / red[0];
}

__global__ void k_ln_head(const float* __restrict__ lng, const float* __restrict__ lnb,
                          const float* __restrict__ hW, const float* __restrict__ hb) {
    int row = blockIdx.x, t = threadIdx.x;
    const float* x = g_feat + (long long)row * ATT;
    float loc[6];
    float s = 0.f;
#pragma unroll
    for (int i = 0; i < 6; i++) { loc[i] = x[t + i * 256]; s += loc[i]; }
    __shared__ float red[256];
    red[t] = s; __syncthreads();
    for (int st = 128; st > 0; st >>= 1) { if (t < st) red[t] += red[t + st]; __syncthreads(); }
    float mu = red[0] * (1.f / ATT); __syncthreads();
    float s2 = 0.f;
#pragma unroll
    for (int i = 0; i < 6; i++) { float d = loc[i] - mu; s2 += d * d; }
    red[t] = s2; __syncthreads();
    for (int st = 128; st > 0; st >>= 1) { if (t < st) red[t] += red[t + st]; __syncthreads(); }
    float inv = rsqrtf(red[0] * (1.f / ATT) + EPSV); __syncthreads();
    float o = 0.f;
#pragma unroll
    for (int i = 0; i < 6; i++) {
        int j = t + i * 256;
        float nv = lng[j] * (loc[i] - mu) * inv + lnb[j];
        o += nv * hW[j];
    }
    red[t] = o; __syncthreads();
    for (int st = 128; st > 0; st >>= 1) { if (t < st) red[t] += red[t + st]; __syncthreads(); }
    if (t == 0) g_logits[row] = red[0] + hb[0];
}

__global__ void k_final(const float* __restrict__ ea, float* __restrict__ out) {
    int idx = blockIdx.x * 256 + threadIdx.x;
    if (idx < BGR * 128) {
        int i0 = 2 * idx, i1 = i0 + 1;
        float v0 = g_logits[i0], v1 = g_logits[i1];
        float c0 = ea[2 * g_kidx[i0] + 1], c1 = ea[2 * g_kidx[i1] + 1];
        int m = (v1 < v0) ? 1 : 0;
        out[idx * 2 + 0] = (float)g_esrc[i0];
        out[idx * 2 + 1] = (float)g_edst[i0];
        out[32768 + idx] = m ? v1 : v0;
        out[49152 + idx] = m ? c1 : c0;
    }
}

// ---------------- host-side GEMM dispatch ----------------
template<bool TB, bool ACC, bool RELU, bool HASB, bool GAT = false>
static void gemm(const float* A, const float* B, float* C, const float* bias,
                 int M, int N, int K, int lda, int ldb, int ldc,
                 long long sA, long long sB, long long sC, long long sBias,
                 float alpha, int batch,
                 const float* T1 = nullptr, const float* T2 = nullptr) {
    dim3 grid(N / 128, M / 128, batch);
    tgemm<TB, ACC, RELU, HASB, GAT><<<grid, 256>>>(
        A, B, C, bias, M, N, K, lda, ldb, ldc, sA, sB, sC, sBias, alpha, T1, T2);
}

static float* sym(const void* s) {
    void* p = nullptr;
    cudaGetSymbolAddress(&p, s);
    return (float*)p;
}

extern "C" void kernel_launch(void* const* d_in, const int* in_sizes, int n_in,
                              void* d_out, int out_size) {
    const float* x       = (const float*)d_in[0];
    const int*   edges   = (const int*)d_in[1];
    const float* ea      = (const float*)d_in[2];
    const float* wembW   = (const float*)d_in[5];
    const float* wembB   = (const float*)d_in[6];
    const float* gc1Wrel = (const float*)d_in[7];
    const float* gc1brel = (const float*)d_in[8];
    const float* gc1Wroot= (const float*)d_in[9];
    const float* gc2Wrel = (const float*)d_in[10];
    const float* gc2brel = (const float*)d_in[11];
    const float* gc2Wroot= (const float*)d_in[12];
    const float* gnw     = (const float*)d_in[13];
    const float* gnb     = (const float*)d_in[14];
    const float* gnms    = (const float*)d_in[15];
    const float* eW      = (const float*)d_in[16];
    const float* ebias   = (const float*)d_in[17];
    const float* qkvW    = (const float*)d_in[18];
    const float* qkvb    = (const float*)d_in[19];
    const float* inWq    = (const float*)d_in[20];
    const float* inWk    = (const float*)d_in[21];
    const float* inWv    = (const float*)d_in[22];
    const float* inbq    = (const float*)d_in[23];
    const float* inbv    = (const float*)d_in[25];
    const float* outW    = (const float*)d_in[26];
    const float* outb    = (const float*)d_in[27];
    const float* lng     = (const float*)d_in[28];
    const float* lnb     = (const float*)d_in[29];
    const float* hW      = (const float*)d_in[30];
    const float* hb      = (const float*)d_in[31];
    (void)in_sizes; (void)n_in; (void)out_size;

    float* agg1 = sym(g_agg1);  float* agg2 = sym(g_agg2);
    float* h1   = sym(g_h1);    float* h2   = sym(g_h2);
    float* feat = sym(g_feat);
    float* Wq   = sym(g_Wq);    float* Wk  = sym(g_Wk);   float* Wv  = sym(g_Wv);
    float* Wqk  = sym(g_Wqk);   float* Wvo = sym(g_Wvo);
    float* bq   = sym(g_bq);    float* bv  = sym(g_bv);
    float* rvec = sym(g_rvec);  float* bvo = sym(g_bvo);  float* rv  = sym(g_rv);
    float* G    = sym(g_G);     float* FVo = sym(g_FVo);  float* S   = sym(g_S);
    float* P1   = sym(g_P1);    float* P3  = sym(g_P3);
    float* Q1   = sym(g_Q1);    float* Q3  = sym(g_Q3);

    const float scale = 1.0f / sqrtf((float)ATT);

    // ---- weight folds first (independent of activations) ----
    // kernel-launch indexes: 0,1,2 = qkv folds; 3 = Wqk fold (ncu profiles index 3)
    gemm<false, false, false, false>(qkvW + 0,    inWq, Wq, nullptr, ATT, ATT, ATT, 3 * ATT, ATT, ATT, 0, 0, 0, 0, 1.f, 1);
    gemm<false, false, false, false>(qkvW + ATT,  inWk, Wk, nullptr, ATT, ATT, ATT, 3 * ATT, ATT, ATT, 0, 0, 0, 0, 1.f, 1);
    gemm<false, false, false, false>(qkvW + 2*ATT,inWv, Wv, nullptr, ATT, ATT, ATT, 3 * ATT, ATT, ATT, 0, 0, 0, 0, 1.f, 1);
    gemm<true,  false, false, false>(Wq, Wk, Wqk, nullptr, ATT, ATT, ATT, ATT, ATT, ATT, 0, 0, 0, 0, scale, 1);   // PROFILED
    gemm<false, false, false, false>(Wv, outW, Wvo, nullptr, ATT, ATT, ATT, ATT, ATT, ATT, 0, 0, 0, 0, 1.f, 1);
    k_vecmat<<<ATT / 256, 256>>>(qkvb + 0,     inWq, inbq, bq, ATT, ATT, ATT);
    k_vecmat<<<ATT / 256, 256>>>(qkvb + 2*ATT, inWv, inbv, bv, ATT, ATT, ATT);
    k_matvecr<<<ATT, 256>>>(Wk, bq, rvec, scale);           // r = scale * Wk_eff @ bq_eff
    k_vecmat<<<ATT / 256, 256>>>(bv, outW, outb, bvo, ATT, ATT, ATT);

    // ---- GNN front-end ----
    k_zero<<<(NTOT * FIN + 255) / 256, 256>>>(agg1, NTOT * FIN);
    k_zero<<<(NTOT * H1D + 255) / 256, 256>>>(agg2, NTOT * H1D);
    k_edgew<<<EDIR / 256, 256>>>(ea, wembW, wembB);
    k_sc1<<<EDIR / 256, 256>>>(edges, x);
    k_gc1<<<NTOT * H1D / 256, 256>>>(x, gc1Wrel, gc1brel, gc1Wroot);
    k_sc2<<<EDIR, 64>>>(edges);
    gemm<false, false, false, false>(agg2, gc2Wrel, h2, nullptr,
                                     NTOT, H2D, H1D, H1D, H2D, H2D, 0, 0, 0, 0, 1.f, 1);
    gemm<false, true, true, true>(h1, gc2Wroot, h2, gc2brel,
                                  NTOT, H2D, H1D, H1D, H2D, H2D, 0, 0, 0, 0, 1.f, 1);
    k_gnorm<<<BGR, H2D>>>(gnw, gnb, gnms);

    // ---- edge selection + sort + feature assembly ----
    k_sort<<<BGR, 256>>>(edges);
    k_feat<<<EKEEP, 256>>>(ea, eW, ebias);

    // ---- decomposed projections: G = P1[src] + emb@Wqk_mid + P3[dst] ----
    gemm<false, false, false, false>(h2, Wqk, P1, nullptr,
                                     NTOT, ATT, 512, H2D, ATT, ATT, 0, 0, 0, 0, 1.f, 1);
    gemm<false, false, false, false>(h2, Wqk + (long long)1024 * ATT, P3, nullptr,
                                     NTOT, ATT, 512, H2D, ATT, ATT, 0, 0, 0, 0, 1.f, 1);
    gemm<false, false, false, false>(h2, Wvo, Q1, nullptr,
                                     NTOT, ATT, 512, H2D, ATT, ATT, 0, 0, 0, 0, 1.f, 1);
    gemm<false, false, false, false>(h2, Wvo + (long long)1024 * ATT, Q3, nullptr,
                                     NTOT, ATT, 512, H2D, ATT, ATT, 0, 0, 0, 0, 1.f, 1);
    // edge-level mid products with fused gather-add epilogue
    gemm<false, false, false, false, true>(feat + 512, Wqk + (long long)512 * ATT, G, nullptr,
                                           EKEEP, ATT, 512, ATT, ATT, ATT,
                                           0, 0, 0, 0, 1.f, 1, P1, P3);
    gemm<false, false, false, true, true>(feat + 512, Wvo + (long long)512 * ATT, FVo, bvo,
                                          EKEEP, ATT, 512, ATT, ATT, ATT,
                                          0, 0, 0, 0, 1.f, 1, Q1, Q3);

    // ---- attention ----
    k_rowdot<<<EKEEP, 256>>>();                             // rv = feat @ rvec
    gemm<true, false, false, true>(G, feat, S, rv,
                                   EU, EU, ATT, ATT, ATT, EU,
                                   (long long)EU * ATT, (long long)EU * ATT,
                                   (long long)EU * EU, EU, 1.f, BGR);
    k_softmax<<<EKEEP, 256>>>();
    gemm<false, true, false, false>(S, FVo, feat, nullptr,
                                    EU, ATT, EU, EU, ATT, ATT,
                                    (long long)EU * EU, (long long)EU * ATT,
                                    (long long)EU * ATT, 0, 1.f, BGR);

    // ---- LN + head + pairing ----
    k_ln_head<<<EKEEP, 256>>>(lng, lnb, hW, hb);
    k_final<<<(BGR * 128) / 256, 256>>>(ea, (float*)d_out);
}

// round 9
// speedup vs baseline: 1.4781x; 1.0613x over previous
#include <cuda_runtime.h>
#include <math.h>
#include <stdint.h>

// ---------------- problem constants ----------------
#define NTOT  8192
#define BGR   128
#define NPER  64
#define EDIR  65536
#define EKEEP 32768
#define EU    256
#define FIN   5
#define H1D   256
#define H2D   512
#define ATT   1536
#define EPSV  1e-5f

// ---------------- scratch (device globals; no allocation allowed) ----------------
__device__ float g_w[EDIR];
__device__ float g_agg1[NTOT * FIN];
__device__ float g_h1[NTOT * H1D];
__device__ float g_agg2[NTOT * H1D];
__device__ float g_h2[NTOT * H2D];
__device__ int   g_esrc[EKEEP];
__device__ int   g_edst[EKEEP];
__device__ int   g_kidx[EKEEP];
__device__ float g_feat[(size_t)EKEEP * ATT];
__device__ float g_Wq[ATT * ATT];
__device__ float g_Wk[ATT * ATT];
__device__ float g_Wv[ATT * ATT];
__device__ float g_Wqk[ATT * ATT];
__device__ float g_Wvo[ATT * ATT];
__device__ float g_bq[ATT];
__device__ float g_bv[ATT];
__device__ float g_rvec[ATT];
__device__ float g_bvo[ATT];
__device__ float g_rv[EKEEP];
__device__ float g_G[(size_t)EKEEP * ATT];
__device__ float g_FVo[(size_t)EKEEP * ATT];
__device__ float g_P1[(size_t)NTOT * ATT];
__device__ float g_P3[(size_t)NTOT * ATT];
__device__ float g_Q1[(size_t)NTOT * ATT];
__device__ float g_Q3[(size_t)NTOT * ATT];
__device__ float g_S[(size_t)BGR * EU * EU];
__device__ float g_logits[EKEEP];

// ---------------- tf32 helpers ----------------
__device__ __forceinline__ uint32_t f2tf(float x) {
    uint32_t r;
    asm("cvt.rna.tf32.f32 %0, %1;" : "=r"(r) : "f"(x));
    return r;
}
__device__ __forceinline__ void tfsplit(float x, uint32_t& b, uint32_t& s) {
    b = f2tf(x);
    s = f2tf(x - __uint_as_float(b));
}
__device__ __forceinline__ void cp16(void* smem_dst, const void* gsrc) {
    uint32_t s = (uint32_t)__cvta_generic_to_shared(smem_dst);
    asm volatile("cp.async.ca.shared.global [%0], [%1], 16;\n" :: "r"(s), "l"(gsrc));
}
#define CP_COMMIT() asm volatile("cp.async.commit_group;\n" ::: "memory")
#define CP_WAIT1()  asm volatile("cp.async.wait_group 1;\n" ::: "memory")

// ---------------- 3xTF32 tensor-core GEMM: 128x128x16 tiles ----------------
// C = alpha * A @ B (or A @ B^T) [+ C] [+ bias] [relu] [+ gathered tables], batched.
// fp32-comparable precision: Ab*Bb + Ab*Bs + As*Bb (identical op order to prior rounds).
// fp32 staged in smem via cp.async, split to tf32 at fragment-load time (halves
// smem bytes + STS + LDS vs pre-split). 2-stage double buffer, unrolled so stage
// indices are compile-time (no runtime-index register blowup).
// GAT: C[row] += T1[g_esrc[row]*ATT + col] + T2[g_edst[row]*ATT + col]  (bz==0 use).
template<bool TB, bool ACC, bool RELU, bool HASB, bool GAT>
__global__ __launch_bounds__(256) void tgemm(
    const float* __restrict__ A, const float* __restrict__ B,
    float* __restrict__ C, const float* __restrict__ bias,
    int M, int N, int K, int lda, int ldb, int ldc,
    long long sA, long long sB, long long sC, long long sBias, float alpha,
    const float* __restrict__ T1, const float* __restrict__ T2)
{
    constexpr int BFS = TB ? (128 * 20) : (16 * 136);
    __shared__ float Af[2][128 * 20];   // [m][k], stride 20: banks 20g+q conflict-free
    __shared__ float Bf[2][BFS];        // TB: [n][k] stride 20; else [k][n] stride 136

    const int t  = threadIdx.x;
    const int bx = blockIdx.x, by = blockIdx.y, bz = blockIdx.z;
    const int n0 = bx * 128;
    const float* Ab = A + (long long)bz * sA + (long long)(by * 128) * lda;
    const float* Bb = B + (long long)bz * sB;
    float* Cb = C + (long long)bz * sC + (long long)(by * 128) * ldc + n0;

    const int lane = t & 31, wid = t >> 5;
    const int grp = lane >> 2, qid = lane & 3;
    const int wm = (wid & 1) * 64;
    const int wn = (wid >> 1) * 32;

    float acc[4][4][4];
#pragma unroll
    for (int mi = 0; mi < 4; mi++)
#pragma unroll
        for (int nj = 0; nj < 4; nj++)
#pragma unroll
            for (int h = 0; h < 4; h++) acc[mi][nj][h] = 0.f;

    const int ar = t >> 2, ac = (t & 3) * 4;    // A: rows ar, ar+64; 16B at k-offset ac
    const int br = t >> 5, bc = (t & 31) * 4;   // B non-TB: rows br, br+8
    const int tr = t >> 1, tk = (t & 1) * 8;    // B TB: n-row tr, k cols tk..tk+7

    auto copy_tile = [&](int st, int k0) {
        cp16(&Af[st][ar * 20 + ac],        Ab + (long long)ar * lda + k0 + ac);
        cp16(&Af[st][(ar + 64) * 20 + ac], Ab + (long long)(ar + 64) * lda + k0 + ac);
        if (TB) {
            cp16(&Bf[st][tr * 20 + tk],     Bb + (long long)(n0 + tr) * ldb + k0 + tk);
            cp16(&Bf[st][tr * 20 + tk + 4], Bb + (long long)(n0 + tr) * ldb + k0 + tk + 4);
        } else {
            cp16(&Bf[st][br * 136 + bc],       Bb + (long long)(k0 + br) * ldb + n0 + bc);
            cp16(&Bf[st][(br + 8) * 136 + bc], Bb + (long long)(k0 + br + 8) * ldb + n0 + bc);
        }
    };

    auto compute = [&](const float* A_s, const float* B_s) {
#pragma unroll
        for (int ks = 0; ks < 2; ks++) {
            const int k0 = ks * 8;
            uint32_t aB[4][4], aS[4][4];
#pragma unroll
            for (int mi = 0; mi < 4; mi++) {
                int r0 = wm + mi * 16 + grp;
                float f0 = A_s[r0 * 20 + k0 + qid];
                float f1 = A_s[(r0 + 8) * 20 + k0 + qid];
                float f2 = A_s[r0 * 20 + k0 + qid + 4];
                float f3 = A_s[(r0 + 8) * 20 + k0 + qid + 4];
                tfsplit(f0, aB[mi][0], aS[mi][0]);
                tfsplit(f1, aB[mi][1], aS[mi][1]);
                tfsplit(f2, aB[mi][2], aS[mi][2]);
                tfsplit(f3, aB[mi][3], aS[mi][3]);
            }
#pragma unroll
            for (int nj = 0; nj < 4; nj++) {
                int c0 = wn + nj * 8 + grp;
                float bf0 = TB ? B_s[c0 * 20 + k0 + qid]     : B_s[(k0 + qid) * 136 + c0];
                float bf1 = TB ? B_s[c0 * 20 + k0 + qid + 4] : B_s[(k0 + qid + 4) * 136 + c0];
                uint32_t b0B, b0S, b1B, b1S;
                tfsplit(bf0, b0B, b0S);
                tfsplit(bf1, b1B, b1S);
#pragma unroll
                for (int mi = 0; mi < 4; mi++) {
                    asm volatile(
                        "mma.sync.aligned.m16n8k8.row.col.f32.tf32.tf32.f32 "
                        "{%0,%1,%2,%3},{%4,%5,%6,%7},{%8,%9},{%0,%1,%2,%3};"
                        : "+f"(acc[mi][nj][0]), "+f"(acc[mi][nj][1]),
                          "+f"(acc[mi][nj][2]), "+f"(acc[mi][nj][3])
                        : "r"(aB[mi][0]), "r"(aB[mi][1]), "r"(aB[mi][2]), "r"(aB[mi][3]),
                          "r"(b0S), "r"(b1S));
                    asm volatile(
                        "mma.sync.aligned.m16n8k8.row.col.f32.tf32.tf32.f32 "
                        "{%0,%1,%2,%3},{%4,%5,%6,%7},{%8,%9},{%0,%1,%2,%3};"
                        : "+f"(acc[mi][nj][0]), "+f"(acc[mi][nj][1]),
                          "+f"(acc[mi][nj][2]), "+f"(acc[mi][nj][3])
                        : "r"(aS[mi][0]), "r"(aS[mi][1]), "r"(aS[mi][2]), "r"(aS[mi][3]),
                          "r"(b0B), "r"(b1B));
                    asm volatile(
                        "mma.sync.aligned.m16n8k8.row.col.f32.tf32.tf32.f32 "
                        "{%0,%1,%2,%3},{%4,%5,%6,%7},{%8,%9},{%0,%1,%2,%3};"
                        : "+f"(acc[mi][nj][0]), "+f"(acc[mi][nj][1]),
                          "+f"(acc[mi][nj][2]), "+f"(acc[mi][nj][3])
                        : "r"(aB[mi][0]), "r"(aB[mi][1]), "r"(aB[mi][2]), "r"(aB[mi][3]),
                          "r"(b0B), "r"(b1B));
                }
            }
        }
    };

    const int nk = K / 16;   // nk is even for all call sites (K % 32 == 0)
    copy_tile(0, 0);
    CP_COMMIT();
    copy_tile(1, 16);
    CP_COMMIT();

    for (int kc = 0; kc < nk; kc += 2) {
        // ---- stage 0 ----
        CP_WAIT1();              // stage-0 data arrived (own thread's groups)
        __syncthreads();         // publish to all warps; all past previous stage-0 reads
        compute(Af[0], Bf[0]);
        __syncthreads();         // all warps done reading stage 0
        if (kc + 2 < nk) copy_tile(0, (kc + 2) * 16);
        CP_COMMIT();
        // ---- stage 1 ----
        CP_WAIT1();
        __syncthreads();
        compute(Af[1], Bf[1]);
        __syncthreads();
        if (kc + 3 < nk) copy_tile(1, (kc + 3) * 16);
        CP_COMMIT();
    }

    // epilogue
#pragma unroll
    for (int mi = 0; mi < 4; mi++) {
#pragma unroll
        for (int nj = 0; nj < 4; nj++) {
            int row = wm + mi * 16 + grp;
            int col = wn + nj * 8 + qid * 2;
#pragma unroll
            for (int h = 0; h < 2; h++) {
                int r = row + h * 8;
                float v0 = acc[mi][nj][h * 2 + 0] * alpha;
                float v1 = acc[mi][nj][h * 2 + 1] * alpha;
                if (HASB) {
                    const float* bp = bias + (long long)bz * sBias + n0 + col;
                    v0 += bp[0]; v1 += bp[1];
                }
                if (GAT) {
                    int e = by * 128 + r;
                    int es = g_esrc[e], ed = g_edst[e];
                    float2 t1 = *reinterpret_cast<const float2*>(&T1[(long long)es * ATT + n0 + col]);
                    float2 t2 = *reinterpret_cast<const float2*>(&T2[(long long)ed * ATT + n0 + col]);
                    v0 += t1.x + t2.x; v1 += t1.y + t2.y;
                }
                float2* cp = reinterpret_cast<float2*>(Cb + (long long)r * ldc + col);
                if (ACC) { float2 c = *cp; v0 += c.x; v1 += c.y; }
                if (RELU) { v0 = fmaxf(v0, 0.f); v1 = fmaxf(v1, 0.f); }
                *cp = make_float2(v0, v1);
            }
        }
    }
}

// ---------------- small kernels ----------------
__global__ void k_zero(float* p, int n) {
    int i = blockIdx.x * 256 + threadIdx.x;
    if (i < n) p[i] = 0.f;
}

__global__ void k_edgew(const float* __restrict__ ea, const float* __restrict__ W,
                        const float* __restrict__ b) {
    int e = blockIdx.x * 256 + threadIdx.x;
    if (e < EDIR) {
        float a = ea[2 * e], c = ea[2 * e + 1];
        float v = a * W[0] + ((c < 0.5f) ? W[1] : W[2]) + b[0];
        g_w[e] = fmaxf(v, 0.f);
    }
}

__global__ void k_sc1(const int* __restrict__ edges, const float* __restrict__ x) {
    int e = blockIdx.x * 256 + threadIdx.x;
    if (e < EDIR) {
        int s = edges[e], d = edges[EDIR + e];
        float wv = g_w[e];
        if (wv != 0.f) {
#pragma unroll
            for (int f = 0; f < FIN; f++)
                atomicAdd(&g_agg1[d * FIN + f], wv * x[s * FIN + f]);
        }
    }
}

__global__ void k_gc1(const float* __restrict__ x, const float* __restrict__ Wrel,
                      const float* __restrict__ brel, const float* __restrict__ Wroot) {
    int idx = blockIdx.x * 256 + threadIdx.x;
    int n = idx >> 8, j = idx & 255;
    float s = brel[j];
#pragma unroll
    for (int f = 0; f < FIN; f++) {
        s += g_agg1[n * FIN + f] * Wrel[f * H1D + j];
        s += x[n * FIN + f] * Wroot[f * H1D + j];
    }
    g_h1[idx] = fmaxf(s, 0.f);
}

__global__ void k_sc2(const int* __restrict__ edges) {
    int e = blockIdx.x;
    int t = threadIdx.x;
    int s = edges[e], d = edges[EDIR + e];
    float wv = g_w[e];
    if (wv == 0.f) return;
    float4 hv = *reinterpret_cast<const float4*>(&g_h1[s * H1D + t * 4]);
    atomicAdd(&g_agg2[d * H1D + t * 4 + 0], wv * hv.x);
    atomicAdd(&g_agg2[d * H1D + t * 4 + 1], wv * hv.y);
    atomicAdd(&g_agg2[d * H1D + t * 4 + 2], wv * hv.z);
    atomicAdd(&g_agg2[d * H1D + t * 4 + 3], wv * hv.w);
}

__global__ void k_gnorm(const float* __restrict__ gw, const float* __restrict__ gb,
                        const float* __restrict__ gms) {
    int g = blockIdx.x, j = threadIdx.x;
    float s = 0.f;
    for (int n = 0; n < NPER; n++) s += g_h2[((g << 6) + n) * H2D + j];
    float mean = s * (1.f / NPER);
    float ms = gms[j];
    float off = ms * mean;
    float s2 = 0.f;
    for (int n = 0; n < NPER; n++) {
        float c = g_h2[((g << 6) + n) * H2D + j] - off;
        s2 += c * c;
    }
    float inv = rsqrtf(s2 * (1.f / NPER) + EPSV);
    float wv = gw[j], bv = gb[j];
    for (int n = 0; n < NPER; n++) {
        int idx = ((g << 6) + n) * H2D + j;
        g_h2[idx] = wv * (g_h2[idx] - off) * inv + bv;
    }
}

__global__ void k_sort(const int* __restrict__ edges) {
    __shared__ unsigned int key[256];
    int g = blockIdx.x, t = threadIdx.x;
    int ge = g * 512 + 256 + t;
    int s = edges[ge], d = edges[EDIR + ge];
    unsigned int k = ((unsigned)((s - (g << 6)) * 64 + (d - (g << 6))) << 8) | (unsigned)t;
    key[t] = k;
    __syncthreads();
    for (int kk = 2; kk <= 256; kk <<= 1) {
        for (int j = kk >> 1; j > 0; j >>= 1) {
            int ixj = t ^ j;
            if (ixj > t) {
                unsigned a = key[t], b = key[ixj];
                bool up = (t & kk) == 0;
                if ((a > b) == up) { key[t] = b; key[ixj] = a; }
            }
            __syncthreads();
        }
    }
    int slot = key[t] & 255;
    int ge2 = g * 512 + 256 + slot;
    int i = g * 256 + t;
    g_esrc[i] = edges[ge2];
    g_edst[i] = edges[EDIR + ge2];
    g_kidx[i] = ge2;
}

__global__ void k_feat(const float* __restrict__ ea, const float* __restrict__ eW,
                       const float* __restrict__ eb) {
    int i = blockIdx.x, t = threadIdx.x;
    int s = g_esrc[i], d = g_edst[i], ke = g_kidx[i];
    float a = ea[2 * ke], c = ea[2 * ke + 1];
    float* F = g_feat + (long long)i * ATT;
    for (int j = t; j < H2D; j += 256) {
        F[j]        = g_h2[s * H2D + j];
        F[1024 + j] = g_h2[d * H2D + j];
        float e = a * eW[j] + ((c < 0.5f) ? eW[512 + j] : eW[1024 + j]) + eb[j];
        F[512 + j] = fmaxf(e, 0.f);
    }
}

__global__ void k_vecmat(const float* __restrict__ x, const float* __restrict__ W,
                         const float* __restrict__ b, float* __restrict__ y,
                         int K, int N, int ldw) {
    int j = blockIdx.x * 256 + threadIdx.x;
    if (j < N) {
        float s = b ? b[j] : 0.f;
        for (int i = 0; i < K; i++) s += x[i] * W[(long long)i * ldw + j];
        y[j] = s;
    }
}

__global__ void k_matvecr(const float* __restrict__ W, const float* __restrict__ x,
                          float* __restrict__ y, float scale) {
    int row = blockIdx.x, t = threadIdx.x;
    float s = 0.f;
    for (int j = t; j < ATT; j += 256) s += W[(long long)row * ATT + j] * x[j];
    __shared__ float red[256];
    red[t] = s; __syncthreads();
    for (int st = 128; st > 0; st >>= 1) { if (t < st) red[t] += red[t + st]; __syncthreads(); }
    if (t == 0) y[row] = red[0] * scale;
}

__global__ void k_rowdot() {
    int row = blockIdx.x, t = threadIdx.x;
    const float* F = g_feat + (long long)row * ATT;
    float s = 0.f;
    for (int j = t; j < ATT; j += 256) s += F[j] * g_rvec[j];
    __shared__ float red[256];
    red[t] = s; __syncthreads();
    for (int st = 128; st > 0; st >>= 1) { if (t < st) red[t] += red[t + st]; __syncthreads(); }
    if (t == 0) g_rv[row] = red[0];
}

__global__ void k_softmax() {
    int rb = blockIdx.x, t = threadIdx.x;
    float v = g_S[(long long)rb * 256 + t];
    __shared__ float red[256];
    red[t] = v; __syncthreads();
    for (int s = 128; s > 0; s >>= 1) { if (t < s) red[t] = fmaxf(red[t], red[t + s]); __syncthreads(); }
    float m = red[0]; __syncthreads();
    float e = __expf(v - m);
    red[t] = e; __syncthreads();
    for (int s = 128; s > 0; s >>= 1) { if (t < s) red[t] += red[t + s]; __syncthreads(); }
    g_S[(long long)rb * 256 + t] = e / red[0];
}

__global__ void k_ln_head(const float* __restrict__ lng, const float* __restrict__ lnb,
                          const float* __restrict__ hW, const float* __restrict__ hb) {
    int row = blockIdx.x, t = threadIdx.x;
    const float* x = g_feat + (long long)row * ATT;
    float loc[6];
    float s = 0.f;
#pragma unroll
    for (int i = 0; i < 6; i++) { loc[i] = x[t + i * 256]; s += loc[i]; }
    __shared__ float red[256];
    red[t] = s; __syncthreads();
    for (int st = 128; st > 0; st >>= 1) { if (t < st) red[t] += red[t + st]; __syncthreads(); }
    float mu = red[0] * (1.f / ATT); __syncthreads();
    float s2 = 0.f;
#pragma unroll
    for (int i = 0; i < 6; i++) { float d = loc[i] - mu; s2 += d * d; }
    red[t] = s2; __syncthreads();
    for (int st = 128; st > 0; st >>= 1) { if (t < st) red[t] += red[t + st]; __syncthreads(); }
    float inv = rsqrtf(red[0] * (1.f / ATT) + EPSV); __syncthreads();
    float o = 0.f;
#pragma unroll
    for (int i = 0; i < 6; i++) {
        int j = t + i * 256;
        float nv = lng[j] * (loc[i] - mu) * inv + lnb[j];
        o += nv * hW[j];
    }
    red[t] = o; __syncthreads();
    for (int st = 128; st > 0; st >>= 1) { if (t < st) red[t] += red[t + st]; __syncthreads(); }
    if (t == 0) g_logits[row] = red[0] + hb[0];
}

__global__ void k_final(const float* __restrict__ ea, float* __restrict__ out) {
    int idx = blockIdx.x * 256 + threadIdx.x;
    if (idx < BGR * 128) {
        int i0 = 2 * idx, i1 = i0 + 1;
        float v0 = g_logits[i0], v1 = g_logits[i1];
        float c0 = ea[2 * g_kidx[i0] + 1], c1 = ea[2 * g_kidx[i1] + 1];
        int m = (v1 < v0) ? 1 : 0;
        out[idx * 2 + 0] = (float)g_esrc[i0];
        out[idx * 2 + 1] = (float)g_edst[i0];
        out[32768 + idx] = m ? v1 : v0;
        out[49152 + idx] = m ? c1 : c0;
    }
}

// ---------------- host-side GEMM dispatch ----------------
template<bool TB, bool ACC, bool RELU, bool HASB, bool GAT = false>
static void gemm(const float* A, const float* B, float* C, const float* bias,
                 int M, int N, int K, int lda, int ldb, int ldc,
                 long long sA, long long sB, long long sC, long long sBias,
                 float alpha, int batch,
                 const float* T1 = nullptr, const float* T2 = nullptr) {
    dim3 grid(N / 128, M / 128, batch);
    tgemm<TB, ACC, RELU, HASB, GAT><<<grid, 256>>>(
        A, B, C, bias, M, N, K, lda, ldb, ldc, sA, sB, sC, sBias, alpha, T1, T2);
}

static float* sym(const void* s) {
    void* p = nullptr;
    cudaGetSymbolAddress(&p, s);
    return (float*)p;
}

extern "C" void kernel_launch(void* const* d_in, const int* in_sizes, int n_in,
                              void* d_out, int out_size) {
    const float* x       = (const float*)d_in[0];
    const int*   edges   = (const int*)d_in[1];
    const float* ea      = (const float*)d_in[2];
    const float* wembW   = (const float*)d_in[5];
    const float* wembB   = (const float*)d_in[6];
    const float* gc1Wrel = (const float*)d_in[7];
    const float* gc1brel = (const float*)d_in[8];
    const float* gc1Wroot= (const float*)d_in[9];
    const float* gc2Wrel = (const float*)d_in[10];
    const float* gc2brel = (const float*)d_in[11];
    const float* gc2Wroot= (const float*)d_in[12];
    const float* gnw     = (const float*)d_in[13];
    const float* gnb     = (const float*)d_in[14];
    const float* gnms    = (const float*)d_in[15];
    const float* eW      = (const float*)d_in[16];
    const float* ebias   = (const float*)d_in[17];
    const float* qkvW    = (const float*)d_in[18];
    const float* qkvb    = (const float*)d_in[19];
    const float* inWq    = (const float*)d_in[20];
    const float* inWk    = (const float*)d_in[21];
    const float* inWv    = (const float*)d_in[22];
    const float* inbq    = (const float*)d_in[23];
    const float* inbv    = (const float*)d_in[25];
    const float* outW    = (const float*)d_in[26];
    const float* outb    = (const float*)d_in[27];
    const float* lng     = (const float*)d_in[28];
    const float* lnb     = (const float*)d_in[29];
    const float* hW      = (const float*)d_in[30];
    const float* hb      = (const float*)d_in[31];
    (void)in_sizes; (void)n_in; (void)out_size;

    float* agg1 = sym(g_agg1);  float* agg2 = sym(g_agg2);
    float* h1   = sym(g_h1);    float* h2   = sym(g_h2);
    float* feat = sym(g_feat);
    float* Wq   = sym(g_Wq);    float* Wk  = sym(g_Wk);   float* Wv  = sym(g_Wv);
    float* Wqk  = sym(g_Wqk);   float* Wvo = sym(g_Wvo);
    float* bq   = sym(g_bq);    float* bv  = sym(g_bv);
    float* rvec = sym(g_rvec);  float* bvo = sym(g_bvo);  float* rv  = sym(g_rv);
    float* G    = sym(g_G);     float* FVo = sym(g_FVo);  float* S   = sym(g_S);
    float* P1   = sym(g_P1);    float* P3  = sym(g_P3);
    float* Q1   = sym(g_Q1);    float* Q3  = sym(g_Q3);

    const float scale = 1.0f / sqrtf((float)ATT);

    // ---- weight folds first; launch index 3 = Wqk fold (ncu profiles index 3) ----
    gemm<false, false, false, false>(qkvW + 0,    inWq, Wq, nullptr, ATT, ATT, ATT, 3 * ATT, ATT, ATT, 0, 0, 0, 0, 1.f, 1);
    gemm<false, false, false, false>(qkvW + ATT,  inWk, Wk, nullptr, ATT, ATT, ATT, 3 * ATT, ATT, ATT, 0, 0, 0, 0, 1.f, 1);
    gemm<false, false, false, false>(qkvW + 2*ATT,inWv, Wv, nullptr, ATT, ATT, ATT, 3 * ATT, ATT, ATT, 0, 0, 0, 0, 1.f, 1);
    gemm<true,  false, false, false>(Wq, Wk, Wqk, nullptr, ATT, ATT, ATT, ATT, ATT, ATT, 0, 0, 0, 0, scale, 1);   // PROFILED
    gemm<false, false, false, false>(Wv, outW, Wvo, nullptr, ATT, ATT, ATT, ATT, ATT, ATT, 0, 0, 0, 0, 1.f, 1);
    k_vecmat<<<ATT / 256, 256>>>(qkvb + 0,     inWq, inbq, bq, ATT, ATT, ATT);
    k_vecmat<<<ATT / 256, 256>>>(qkvb + 2*ATT, inWv, inbv, bv, ATT, ATT, ATT);
    k_matvecr<<<ATT, 256>>>(Wk, bq, rvec, scale);           // r = scale * Wk_eff @ bq_eff
    k_vecmat<<<ATT / 256, 256>>>(bv, outW, outb, bvo, ATT, ATT, ATT);

    // ---- GNN front-end ----
    k_zero<<<(NTOT * FIN + 255) / 256, 256>>>(agg1, NTOT * FIN);
    k_zero<<<(NTOT * H1D + 255) / 256, 256>>>(agg2, NTOT * H1D);
    k_edgew<<<EDIR / 256, 256>>>(ea, wembW, wembB);
    k_sc1<<<EDIR / 256, 256>>>(edges, x);
    k_gc1<<<NTOT * H1D / 256, 256>>>(x, gc1Wrel, gc1brel, gc1Wroot);
    k_sc2<<<EDIR, 64>>>(edges);
    gemm<false, false, false, false>(agg2, gc2Wrel, h2, nullptr,
                                     NTOT, H2D, H1D, H1D, H2D, H2D, 0, 0, 0, 0, 1.f, 1);
    gemm<false, true, true, true>(h1, gc2Wroot, h2, gc2brel,
                                  NTOT, H2D, H1D, H1D, H2D, H2D, 0, 0, 0, 0, 1.f, 1);
    k_gnorm<<<BGR, H2D>>>(gnw, gnb, gnms);

    // ---- edge selection + sort + feature assembly ----
    k_sort<<<BGR, 256>>>(edges);
    k_feat<<<EKEEP, 256>>>(ea, eW, ebias);

    // ---- decomposed projections: G = P1[src] + emb@Wqk_mid + P3[dst] ----
    gemm<false, false, false, false>(h2, Wqk, P1, nullptr,
                                     NTOT, ATT, 512, H2D, ATT, ATT, 0, 0, 0, 0, 1.f, 1);
    gemm<false, false, false, false>(h2, Wqk + (long long)1024 * ATT, P3, nullptr,
                                     NTOT, ATT, 512, H2D, ATT, ATT, 0, 0, 0, 0, 1.f, 1);
    gemm<false, false, false, false>(h2, Wvo, Q1, nullptr,
                                     NTOT, ATT, 512, H2D, ATT, ATT, 0, 0, 0, 0, 1.f, 1);
    gemm<false, false, false, false>(h2, Wvo + (long long)1024 * ATT, Q3, nullptr,
                                     NTOT, ATT, 512, H2D, ATT, ATT, 0, 0, 0, 0, 1.f, 1);
    // edge-level mid products with fused gather-add epilogue
    gemm<false, false, false, false, true>(feat + 512, Wqk + (long long)512 * ATT, G, nullptr,
                                           EKEEP, ATT, 512, ATT, ATT, ATT,
                                           0, 0, 0, 0, 1.f, 1, P1, P3);
    gemm<false, false, false, true, true>(feat + 512, Wvo + (long long)512 * ATT, FVo, bvo,
                                          EKEEP, ATT, 512, ATT, ATT, ATT,
                                          0, 0, 0, 0, 1.f, 1, Q1, Q3);

    // ---- attention ----
    k_rowdot<<<EKEEP, 256>>>();                             // rv = feat @ rvec
    gemm<true, false, false, true>(G, feat, S, rv,
                                   EU, EU, ATT, ATT, ATT, EU,
                                   (long long)EU * ATT, (long long)EU * ATT,
                                   (long long)EU * EU, EU, 1.f, BGR);
    k_softmax<<<EKEEP, 256>>>();
    gemm<false, true, false, false>(S, FVo, feat, nullptr,
                                    EU, ATT, EU, EU, ATT, ATT,
                                    (long long)EU * EU, (long long)EU * ATT,
                                    (long long)EU * ATT, 0, 1.f, BGR);

    // ---- LN + head + pairing ----
    k_ln_head<<<EKEEP, 256>>>(lng, lnb, hW, hb);
    k_final<<<(BGR * 128) / 256, 256>>>(ea, (float*)d_out);
}

// round 10
// speedup vs baseline: 1.5521x; 1.0501x over previous
#include <cuda_runtime.h>
#include <math.h>
#include <stdint.h>

// ---------------- problem constants ----------------
#define NTOT  8192
#define BGR   128
#define NPER  64
#define EDIR  65536
#define EKEEP 32768
#define EU    256
#define FIN   5
#define H1D   256
#define H2D   512
#define ATT   1536
#define EPSV  1e-5f

// ---------------- scratch (device globals; no allocation allowed) ----------------
__device__ float g_w[EDIR];
__device__ float g_agg1[NTOT * FIN];
__device__ float g_h1[NTOT * H1D];
__device__ float g_agg2[NTOT * H1D];
__device__ float g_h2[NTOT * H2D];
__device__ int   g_esrc[EKEEP];
__device__ int   g_edst[EKEEP];
__device__ int   g_kidx[EKEEP];
__device__ float g_feat[(size_t)EKEEP * ATT];
__device__ float g_Wq[ATT * ATT];
__device__ float g_Wk[ATT * ATT];
__device__ float g_Wv[ATT * ATT];
__device__ float g_Wqk[ATT * ATT];
__device__ float g_Wvo[ATT * ATT];
__device__ float g_bq[ATT];
__device__ float g_bv[ATT];
__device__ float g_rvec[ATT];
__device__ float g_bvo[ATT];
__device__ float g_rv[EKEEP];
__device__ float g_G[(size_t)EKEEP * ATT];
__device__ float g_FVo[(size_t)EKEEP * ATT];
__device__ float g_P1[(size_t)NTOT * ATT];
__device__ float g_P3[(size_t)NTOT * ATT];
__device__ float g_Q1[(size_t)NTOT * ATT];
__device__ float g_Q3[(size_t)NTOT * ATT];
__device__ float g_S[(size_t)BGR * EU * EU];
__device__ float g_logits[EKEEP];

// ---------------- tf32 helpers ----------------
__device__ __forceinline__ uint32_t f2tf(float x) {
    uint32_t r;
    asm("cvt.rna.tf32.f32 %0, %1;" : "=r"(r) : "f"(x));
    return r;
}
__device__ __forceinline__ void tfsplit(float x, uint32_t& b, uint32_t& s) {
    b = f2tf(x);
    s = f2tf(x - __uint_as_float(b));
}
__device__ __forceinline__ void cp16(void* smem_dst, const void* gsrc) {
    uint32_t s = (uint32_t)__cvta_generic_to_shared(smem_dst);
    asm volatile("cp.async.ca.shared.global [%0], [%1], 16;\n" :: "r"(s), "l"(gsrc));
}
#define CP_COMMIT() asm volatile("cp.async.commit_group;\n" ::: "memory")
#define CP_WAITG1() asm volatile("cp.async.wait_group 1;\n" ::: "memory")

// ---------------- 3xTF32 tensor-core GEMM: 128x128x16 tiles ----------------
// C = alpha * A @ B (or A @ B^T) [+ C] [+ bias] [relu] [+ gathered tables], batched.
// fp32-comparable precision: Ab*Bb + Ab*Bs + As*Bb (identical op order to prior rounds).
// fp32 staged in smem via cp.async, split to tf32 at fragment-load time.
// 3-stage ring (CUTLASS multistage): body of chunk i copies chunk i+2 into the
// slot of chunk i-1 (finished by all warps at this chunk's single barrier) —
// ONE __syncthreads per K-chunk. Stage indices compile-time via unroll-by-3.
// GAT: C[row] += T1[g_esrc[row]*ATT + col] + T2[g_edst[row]*ATT + col]  (bz==0 use).
template<bool TB, bool ACC, bool RELU, bool HASB, bool GAT>
__global__ __launch_bounds__(256) void tgemm(
    const float* __restrict__ A, const float* __restrict__ B,
    float* __restrict__ C, const float* __restrict__ bias,
    int M, int N, int K, int lda, int ldb, int ldc,
    long long sA, long long sB, long long sC, long long sBias, float alpha,
    const float* __restrict__ T1, const float* __restrict__ T2)
{
    constexpr int ASZ = 128 * 20;                    // floats per A stage (stride 20)
    constexpr int BSZ = TB ? (128 * 20) : (16 * 136);
    extern __shared__ float smf[];
    float* Afp = smf;             // [3][ASZ]
    float* Bfp = smf + 3 * ASZ;   // [3][BSZ]

    const int t  = threadIdx.x;
    const int bx = blockIdx.x, by = blockIdx.y, bz = blockIdx.z;
    const int n0 = bx * 128;
    const float* Ab = A + (long long)bz * sA + (long long)(by * 128) * lda;
    const float* Bb = B + (long long)bz * sB;
    float* Cb = C + (long long)bz * sC + (long long)(by * 128) * ldc + n0;

    const int lane = t & 31, wid = t >> 5;
    const int grp = lane >> 2, qid = lane & 3;
    const int wm = (wid & 1) * 64;
    const int wn = (wid >> 1) * 32;

    float acc[4][4][4];
#pragma unroll
    for (int mi = 0; mi < 4; mi++)
#pragma unroll
        for (int nj = 0; nj < 4; nj++)
#pragma unroll
            for (int h = 0; h < 4; h++) acc[mi][nj][h] = 0.f;

    const int ar = t >> 2, ac = (t & 3) * 4;    // A: rows ar, ar+64; 16B at k-offset ac
    const int br = t >> 5, bc = (t & 31) * 4;   // B non-TB: rows br, br+8
    const int tr = t >> 1, tk = (t & 1) * 8;    // B TB: n-row tr, k cols tk..tk+7

    auto copy_tile = [&](float* As, float* Bs, int k0) {
        cp16(&As[ar * 20 + ac],        Ab + (long long)ar * lda + k0 + ac);
        cp16(&As[(ar + 64) * 20 + ac], Ab + (long long)(ar + 64) * lda + k0 + ac);
        if (TB) {
            cp16(&Bs[tr * 20 + tk],     Bb + (long long)(n0 + tr) * ldb + k0 + tk);
            cp16(&Bs[tr * 20 + tk + 4], Bb + (long long)(n0 + tr) * ldb + k0 + tk + 4);
        } else {
            cp16(&Bs[br * 136 + bc],       Bb + (long long)(k0 + br) * ldb + n0 + bc);
            cp16(&Bs[(br + 8) * 136 + bc], Bb + (long long)(k0 + br + 8) * ldb + n0 + bc);
        }
    };

    auto compute = [&](const float* A_s, const float* B_s) {
#pragma unroll
        for (int ks = 0; ks < 2; ks++) {
            const int k0 = ks * 8;
            uint32_t aB[4][4], aS[4][4];
#pragma unroll
            for (int mi = 0; mi < 4; mi++) {
                int r0 = wm + mi * 16 + grp;
                float f0 = A_s[r0 * 20 + k0 + qid];
                float f1 = A_s[(r0 + 8) * 20 + k0 + qid];
                float f2 = A_s[r0 * 20 + k0 + qid + 4];
                float f3 = A_s[(r0 + 8) * 20 + k0 + qid + 4];
                tfsplit(f0, aB[mi][0], aS[mi][0]);
                tfsplit(f1, aB[mi][1], aS[mi][1]);
                tfsplit(f2, aB[mi][2], aS[mi][2]);
                tfsplit(f3, aB[mi][3], aS[mi][3]);
            }
#pragma unroll
            for (int nj = 0; nj < 4; nj++) {
                int c0 = wn + nj * 8 + grp;
                float bf0 = TB ? B_s[c0 * 20 + k0 + qid]     : B_s[(k0 + qid) * 136 + c0];
                float bf1 = TB ? B_s[c0 * 20 + k0 + qid + 4] : B_s[(k0 + qid + 4) * 136 + c0];
                uint32_t b0B, b0S, b1B, b1S;
                tfsplit(bf0, b0B, b0S);
                tfsplit(bf1, b1B, b1S);
#pragma unroll
                for (int mi = 0; mi < 4; mi++) {
                    asm volatile(
                        "mma.sync.aligned.m16n8k8.row.col.f32.tf32.tf32.f32 "
                        "{%0,%1,%2,%3},{%4,%5,%6,%7},{%8,%9},{%0,%1,%2,%3};"
                        : "+f"(acc[mi][nj][0]), "+f"(acc[mi][nj][1]),
                          "+f"(acc[mi][nj][2]), "+f"(acc[mi][nj][3])
                        : "r"(aB[mi][0]), "r"(aB[mi][1]), "r"(aB[mi][2]), "r"(aB[mi][3]),
                          "r"(b0S), "r"(b1S));
                    asm volatile(
                        "mma.sync.aligned.m16n8k8.row.col.f32.tf32.tf32.f32 "
                        "{%0,%1,%2,%3},{%4,%5,%6,%7},{%8,%9},{%0,%1,%2,%3};"
                        : "+f"(acc[mi][nj][0]), "+f"(acc[mi][nj][1]),
                          "+f"(acc[mi][nj][2]), "+f"(acc[mi][nj][3])
                        : "r"(aS[mi][0]), "r"(aS[mi][1]), "r"(aS[mi][2]), "r"(aS[mi][3]),
                          "r"(b0B), "r"(b1B));
                    asm volatile(
                        "mma.sync.aligned.m16n8k8.row.col.f32.tf32.tf32.f32 "
                        "{%0,%1,%2,%3},{%4,%5,%6,%7},{%8,%9},{%0,%1,%2,%3};"
                        : "+f"(acc[mi][nj][0]), "+f"(acc[mi][nj][1]),
                          "+f"(acc[mi][nj][2]), "+f"(acc[mi][nj][3])
                        : "r"(aB[mi][0]), "r"(aB[mi][1]), "r"(aB[mi][2]), "r"(aB[mi][3]),
                          "r"(b0B), "r"(b1B));
                }
            }
        }
    };

    const int nk = K / 16;   // >= 16 at all call sites
    copy_tile(Afp, Bfp, 0);                       CP_COMMIT();   // chunk 0 -> slot 0
    copy_tile(Afp + ASZ, Bfp + BSZ, 16);          CP_COMMIT();   // chunk 1 -> slot 1

    for (int kc = 0; kc < nk; kc += 3) {
#pragma unroll
        for (int j = 0; j < 3; j++) {
            const int chunk = kc + j;
            if (chunk < nk) {
                CP_WAITG1();          // groups <= chunk complete -> this chunk's data in
                __syncthreads();      // all warps done with slot (j+2)%3 (chunk-1's slot)
                compute(Afp + j * ASZ, Bfp + j * BSZ);
                if (chunk + 2 < nk) {
                    constexpr int js = 0;  // dummy to keep (j+2)%3 compile-time below
                    (void)js;
                    copy_tile(Afp + ((j + 2) % 3) * ASZ,
                              Bfp + ((j + 2) % 3) * BSZ, (chunk + 2) * 16);
                }
                CP_COMMIT();          // one group per chunk (possibly empty)
            }
        }
    }

    // epilogue
#pragma unroll
    for (int mi = 0; mi < 4; mi++) {
#pragma unroll
        for (int nj = 0; nj < 4; nj++) {
            int row = wm + mi * 16 + grp;
            int col = wn + nj * 8 + qid * 2;
#pragma unroll
            for (int h = 0; h < 2; h++) {
                int r = row + h * 8;
                float v0 = acc[mi][nj][h * 2 + 0] * alpha;
                float v1 = acc[mi][nj][h * 2 + 1] * alpha;
                if (HASB) {
                    const float* bp = bias + (long long)bz * sBias + n0 + col;
                    v0 += bp[0]; v1 += bp[1];
                }
                if (GAT) {
                    int e = by * 128 + r;
                    int es = g_esrc[e], ed = g_edst[e];
                    float2 t1 = *reinterpret_cast<const float2*>(&T1[(long long)es * ATT + n0 + col]);
                    float2 t2 = *reinterpret_cast<const float2*>(&T2[(long long)ed * ATT + n0 + col]);
                    v0 += t1.x + t2.x; v1 += t1.y + t2.y;
                }
                float2* cp = reinterpret_cast<float2*>(Cb + (long long)r * ldc + col);
                if (ACC) { float2 c = *cp; v0 += c.x; v1 += c.y; }
                if (RELU) { v0 = fmaxf(v0, 0.f); v1 = fmaxf(v1, 0.f); }
                *cp = make_float2(v0, v1);
            }
        }
    }
}

// ---------------- small kernels ----------------
__global__ void k_zero(float* p, int n) {
    int i = blockIdx.x * 256 + threadIdx.x;
    if (i < n) p[i] = 0.f;
}

__global__ void k_edgew(const float* __restrict__ ea, const float* __restrict__ W,
                        const float* __restrict__ b) {
    int e = blockIdx.x * 256 + threadIdx.x;
    if (e < EDIR) {
        float a = ea[2 * e], c = ea[2 * e + 1];
        float v = a * W[0] + ((c < 0.5f) ? W[1] : W[2]) + b[0];
        g_w[e] = fmaxf(v, 0.f);
    }
}

__global__ void k_sc1(const int* __restrict__ edges, const float* __restrict__ x) {
    int e = blockIdx.x * 256 + threadIdx.x;
    if (e < EDIR) {
        int s = edges[e], d = edges[EDIR + e];
        float wv = g_w[e];
        if (wv != 0.f) {
#pragma unroll
            for (int f = 0; f < FIN; f++)
                atomicAdd(&g_agg1[d * FIN + f], wv * x[s * FIN + f]);
        }
    }
}

__global__ void k_gc1(const float* __restrict__ x, const float* __restrict__ Wrel,
                      const float* __restrict__ brel, const float* __restrict__ Wroot) {
    int idx = blockIdx.x * 256 + threadIdx.x;
    int n = idx >> 8, j = idx & 255;
    float s = brel[j];
#pragma unroll
    for (int f = 0; f < FIN; f++) {
        s += g_agg1[n * FIN + f] * Wrel[f * H1D + j];
        s += x[n * FIN + f] * Wroot[f * H1D + j];
    }
    g_h1[idx] = fmaxf(s, 0.f);
}

__global__ void k_sc2(const int* __restrict__ edges) {
    int e = blockIdx.x;
    int t = threadIdx.x;
    int s = edges[e], d = edges[EDIR + e];
    float wv = g_w[e];
    if (wv == 0.f) return;
    float4 hv = *reinterpret_cast<const float4*>(&g_h1[s * H1D + t * 4]);
    atomicAdd(&g_agg2[d * H1D + t * 4 + 0], wv * hv.x);
    atomicAdd(&g_agg2[d * H1D + t * 4 + 1], wv * hv.y);
    atomicAdd(&g_agg2[d * H1D + t * 4 + 2], wv * hv.z);
    atomicAdd(&g_agg2[d * H1D + t * 4 + 3], wv * hv.w);
}

__global__ void k_gnorm(const float* __restrict__ gw, const float* __restrict__ gb,
                        const float* __restrict__ gms) {
    int g = blockIdx.x, j = threadIdx.x;
    float s = 0.f;
    for (int n = 0; n < NPER; n++) s += g_h2[((g << 6) + n) * H2D + j];
    float mean = s * (1.f / NPER);
    float ms = gms[j];
    float off = ms * mean;
    float s2 = 0.f;
    for (int n = 0; n < NPER; n++) {
        float c = g_h2[((g << 6) + n) * H2D + j] - off;
        s2 += c * c;
    }
    float inv = rsqrtf(s2 * (1.f / NPER) + EPSV);
    float wv = gw[j], bv = gb[j];
    for (int n = 0; n < NPER; n++) {
        int idx = ((g << 6) + n) * H2D + j;
        g_h2[idx] = wv * (g_h2[idx] - off) * inv + bv;
    }
}

__global__ void k_sort(const int* __restrict__ edges) {
    __shared__ unsigned int key[256];
    int g = blockIdx.x, t = threadIdx.x;
    int ge = g * 512 + 256 + t;
    int s = edges[ge], d = edges[EDIR + ge];
    unsigned int k = ((unsigned)((s - (g << 6)) * 64 + (d - (g << 6))) << 8) | (unsigned)t;
    key[t] = k;
    __syncthreads();
    for (int kk = 2; kk <= 256; kk <<= 1) {
        for (int j = kk >> 1; j > 0; j >>= 1) {
            int ixj = t ^ j;
            if (ixj > t) {
                unsigned a = key[t], b = key[ixj];
                bool up = (t & kk) == 0;
                if ((a > b) == up) { key[t] = b; key[ixj] = a; }
            }
            __syncthreads();
        }
    }
    int slot = key[t] & 255;
    int ge2 = g * 512 + 256 + slot;
    int i = g * 256 + t;
    g_esrc[i] = edges[ge2];
    g_edst[i] = edges[EDIR + ge2];
    g_kidx[i] = ge2;
}

__global__ void k_feat(const float* __restrict__ ea, const float* __restrict__ eW,
                       const float* __restrict__ eb) {
    int i = blockIdx.x, t = threadIdx.x;
    int s = g_esrc[i], d = g_edst[i], ke = g_kidx[i];
    float a = ea[2 * ke], c = ea[2 * ke + 1];
    float* F = g_feat + (long long)i * ATT;
    for (int j = t; j < H2D; j += 256) {
        F[j]        = g_h2[s * H2D + j];
        F[1024 + j] = g_h2[d * H2D + j];
        float e = a * eW[j] + ((c < 0.5f) ? eW[512 + j] : eW[1024 + j]) + eb[j];
        F[512 + j] = fmaxf(e, 0.f);
    }
}

__global__ void k_vecmat(const float* __restrict__ x, const float* __restrict__ W,
                         const float* __restrict__ b, float* __restrict__ y,
                         int K, int N, int ldw) {
    int j = blockIdx.x * 256 + threadIdx.x;
    if (j < N) {
        float s = b ? b[j] : 0.f;
        for (int i = 0; i < K; i++) s += x[i] * W[(long long)i * ldw + j];
        y[j] = s;
    }
}

__global__ void k_matvecr(const float* __restrict__ W, const float* __restrict__ x,
                          float* __restrict__ y, float scale) {
    int row = blockIdx.x, t = threadIdx.x;
    float s = 0.f;
    for (int j = t; j < ATT; j += 256) s += W[(long long)row * ATT + j] * x[j];
    __shared__ float red[256];
    red[t] = s; __syncthreads();
    for (int st = 128; st > 0; st >>= 1) { if (t < st) red[t] += red[t + st]; __syncthreads(); }
    if (t == 0) y[row] = red[0] * scale;
}

__global__ void k_rowdot() {
    int row = blockIdx.x, t = threadIdx.x;
    const float* F = g_feat + (long long)row * ATT;
    float s = 0.f;
    for (int j = t; j < ATT; j += 256) s += F[j] * g_rvec[j];
    __shared__ float red[256];
    red[t] = s; __syncthreads();
    for (int st = 128; st > 0; st >>= 1) { if (t < st) red[t] += red[t + st]; __syncthreads(); }
    if (t == 0) g_rv[row] = red[0];
}

__global__ void k_softmax() {
    int rb = blockIdx.x, t = threadIdx.x;
    float v = g_S[(long long)rb * 256 + t];
    __shared__ float red[256];
    red[t] = v; __syncthreads();
    for (int s = 128; s > 0; s >>= 1) { if (t < s) red[t] = fmaxf(red[t], red[t + s]); __syncthreads(); }
    float m = red[0]; __syncthreads();
    float e = __expf(v - m);
    red[t] = e; __syncthreads();
    for (int s = 128; s > 0; s >>= 1) { if (t < s) red[t] += red[t + s]; __syncthreads(); }
    g_S[(long long)rb * 256 + t] = e / red[0];
}

__global__ void k_ln_head(const float* __restrict__ lng, const float* __restrict__ lnb,
                          const float* __restrict__ hW, const float* __restrict__ hb) {
    int row = blockIdx.x, t = threadIdx.x;
    const float* x = g_feat + (long long)row * ATT;
    float loc[6];
    float s = 0.f;
#pragma unroll
    for (int i = 0; i < 6; i++) { loc[i] = x[t + i * 256]; s += loc[i]; }
    __shared__ float red[256];
    red[t] = s; __syncthreads();
    for (int st = 128; st > 0; st >>= 1) { if (t < st) red[t] += red[t + st]; __syncthreads(); }
    float mu = red[0] * (1.f / ATT); __syncthreads();
    float s2 = 0.f;
#pragma unroll
    for (int i = 0; i < 6; i++) { float d = loc[i] - mu; s2 += d * d; }
    red[t] = s2; __syncthreads();
    for (int st = 128; st > 0; st >>= 1) { if (t < st) red[t] += red[t + st]; __syncthreads(); }
    float inv = rsqrtf(red[0] * (1.f / ATT) + EPSV); __syncthreads();
    float o = 0.f;
#pragma unroll
    for (int i = 0; i < 6; i++) {
        int j = t + i * 256;
        float nv = lng[j] * (loc[i] - mu) * inv + lnb[j];
        o += nv * hW[j];
    }
    red[t] = o; __syncthreads();
    for (int st = 128; st > 0; st >>= 1) { if (t < st) red[t] += red[t + st]; __syncthreads(); }
    if (t == 0) g_logits[row] = red[0] + hb[0];
}

__global__ void k_final(const float* __restrict__ ea, float* __restrict__ out) {
    int idx = blockIdx.x * 256 + threadIdx.x;
    if (idx < BGR * 128) {
        int i0 = 2 * idx, i1 = i0 + 1;
        float v0 = g_logits[i0], v1 = g_logits[i1];
        float c0 = ea[2 * g_kidx[i0] + 1], c1 = ea[2 * g_kidx[i1] + 1];
        int m = (v1 < v0) ? 1 : 0;
        out[idx * 2 + 0] = (float)g_esrc[i0];
        out[idx * 2 + 1] = (float)g_edst[i0];
        out[32768 + idx] = m ? v1 : v0;
        out[49152 + idx] = m ? c1 : c0;
    }
}

// ---------------- host-side GEMM dispatch ----------------
template<bool TB, bool ACC, bool RELU, bool HASB, bool GAT = false>
static void gemm(const float* A, const float* B, float* C, const float* bias,
                 int M, int N, int K, int lda, int ldb, int ldc,
                 long long sA, long long sB, long long sC, long long sBias,
                 float alpha, int batch,
                 const float* T1 = nullptr, const float* T2 = nullptr) {
    constexpr int ASZ = 128 * 20;
    constexpr int BSZ = TB ? (128 * 20) : (16 * 136);
    constexpr int SMEM = 3 * (ASZ + BSZ) * 4;
    cudaFuncSetAttribute(tgemm<TB, ACC, RELU, HASB, GAT>,
                         cudaFuncAttributeMaxDynamicSharedMemorySize, SMEM);
    dim3 grid(N / 128, M / 128, batch);
    tgemm<TB, ACC, RELU, HASB, GAT><<<grid, 256, SMEM>>>(
        A, B, C, bias, M, N, K, lda, ldb, ldc, sA, sB, sC, sBias, alpha, T1, T2);
}

static float* sym(const void* s) {
    void* p = nullptr;
    cudaGetSymbolAddress(&p, s);
    return (float*)p;
}

extern "C" void kernel_launch(void* const* d_in, const int* in_sizes, int n_in,
                              void* d_out, int out_size) {
    const float* x       = (const float*)d_in[0];
    const int*   edges   = (const int*)d_in[1];
    const float* ea      = (const float*)d_in[2];
    const float* wembW   = (const float*)d_in[5];
    const float* wembB   = (const float*)d_in[6];
    const float* gc1Wrel = (const float*)d_in[7];
    const float* gc1brel = (const float*)d_in[8];
    const float* gc1Wroot= (const float*)d_in[9];
    const float* gc2Wrel = (const float*)d_in[10];
    const float* gc2brel = (const float*)d_in[11];
    const float* gc2Wroot= (const float*)d_in[12];
    const float* gnw     = (const float*)d_in[13];
    const float* gnb     = (const float*)d_in[14];
    const float* gnms    = (const float*)d_in[15];
    const float* eW      = (const float*)d_in[16];
    const float* ebias   = (const float*)d_in[17];
    const float* qkvW    = (const float*)d_in[18];
    const float* qkvb    = (const float*)d_in[19];
    const float* inWq    = (const float*)d_in[20];
    const float* inWk    = (const float*)d_in[21];
    const float* inWv    = (const float*)d_in[22];
    const float* inbq    = (const float*)d_in[23];
    const float* inbv    = (const float*)d_in[25];
    const float* outW    = (const float*)d_in[26];
    const float* outb    = (const float*)d_in[27];
    const float* lng     = (const float*)d_in[28];
    const float* lnb     = (const float*)d_in[29];
    const float* hW      = (const float*)d_in[30];
    const float* hb      = (const float*)d_in[31];
    (void)in_sizes; (void)n_in; (void)out_size;

    float* agg1 = sym(g_agg1);  float* agg2 = sym(g_agg2);
    float* h1   = sym(g_h1);    float* h2   = sym(g_h2);
    float* feat = sym(g_feat);
    float* Wq   = sym(g_Wq);    float* Wk  = sym(g_Wk);   float* Wv  = sym(g_Wv);
    float* Wqk  = sym(g_Wqk);   float* Wvo = sym(g_Wvo);
    float* bq   = sym(g_bq);    float* bv  = sym(g_bv);
    float* rvec = sym(g_rvec);  float* bvo = sym(g_bvo);  float* rv  = sym(g_rv);
    float* G    = sym(g_G);     float* FVo = sym(g_FVo);  float* S   = sym(g_S);
    float* P1   = sym(g_P1);    float* P3  = sym(g_P3);
    float* Q1   = sym(g_Q1);    float* Q3  = sym(g_Q3);

    const float scale = 1.0f / sqrtf((float)ATT);

    // ---- weight folds first; launch index 3 = Wqk fold (ncu profiles index 3) ----
    gemm<false, false, false, false>(qkvW + 0,    inWq, Wq, nullptr, ATT, ATT, ATT, 3 * ATT, ATT, ATT, 0, 0, 0, 0, 1.f, 1);
    gemm<false, false, false, false>(qkvW + ATT,  inWk, Wk, nullptr, ATT, ATT, ATT, 3 * ATT, ATT, ATT, 0, 0, 0, 0, 1.f, 1);
    gemm<false, false, false, false>(qkvW + 2*ATT,inWv, Wv, nullptr, ATT, ATT, ATT, 3 * ATT, ATT, ATT, 0, 0, 0, 0, 1.f, 1);
    gemm<true,  false, false, false>(Wq, Wk, Wqk, nullptr, ATT, ATT, ATT, ATT, ATT, ATT, 0, 0, 0, 0, scale, 1);   // PROFILED
    gemm<false, false, false, false>(Wv, outW, Wvo, nullptr, ATT, ATT, ATT, ATT, ATT, ATT, 0, 0, 0, 0, 1.f, 1);
    k_vecmat<<<ATT / 256, 256>>>(qkvb + 0,     inWq, inbq, bq, ATT, ATT, ATT);
    k_vecmat<<<ATT / 256, 256>>>(qkvb + 2*ATT, inWv, inbv, bv, ATT, ATT, ATT);
    k_matvecr<<<ATT, 256>>>(Wk, bq, rvec, scale);           // r = scale * Wk_eff @ bq_eff
    k_vecmat<<<ATT / 256, 256>>>(bv, outW, outb, bvo, ATT, ATT, ATT);

    // ---- GNN front-end ----
    k_zero<<<(NTOT * FIN + 255) / 256, 256>>>(agg1, NTOT * FIN);
    k_zero<<<(NTOT * H1D + 255) / 256, 256>>>(agg2, NTOT * H1D);
    k_edgew<<<EDIR / 256, 256>>>(ea, wembW, wembB);
    k_sc1<<<EDIR / 256, 256>>>(edges, x);
    k_gc1<<<NTOT * H1D / 256, 256>>>(x, gc1Wrel, gc1brel, gc1Wroot);
    k_sc2<<<EDIR, 64>>>(edges);
    gemm<false, false, false, false>(agg2, gc2Wrel, h2, nullptr,
                                     NTOT, H2D, H1D, H1D, H2D, H2D, 0, 0, 0, 0, 1.f, 1);
    gemm<false, true, true, true>(h1, gc2Wroot, h2, gc2brel,
                                  NTOT, H2D, H1D, H1D, H2D, H2D, 0, 0, 0, 0, 1.f, 1);
    k_gnorm<<<BGR, H2D>>>(gnw, gnb, gnms);

    // ---- edge selection + sort + feature assembly ----
    k_sort<<<BGR, 256>>>(edges);
    k_feat<<<EKEEP, 256>>>(ea, eW, ebias);

    // ---- decomposed projections: G = P1[src] + emb@Wqk_mid + P3[dst] ----
    gemm<false, false, false, false>(h2, Wqk, P1, nullptr,
                                     NTOT, ATT, 512, H2D, ATT, ATT, 0, 0, 0, 0, 1.f, 1);
    gemm<false, false, false, false>(h2, Wqk + (long long)1024 * ATT, P3, nullptr,
                                     NTOT, ATT, 512, H2D, ATT, ATT, 0, 0, 0, 0, 1.f, 1);
    gemm<false, false, false, false>(h2, Wvo, Q1, nullptr,
                                     NTOT, ATT, 512, H2D, ATT, ATT, 0, 0, 0, 0, 1.f, 1);
    gemm<false, false, false, false>(h2, Wvo + (long long)1024 * ATT, Q3, nullptr,
                                     NTOT, ATT, 512, H2D, ATT, ATT, 0, 0, 0, 0, 1.f, 1);
    // edge-level mid products with fused gather-add epilogue
    gemm<false, false, false, false, true>(feat + 512, Wqk + (long long)512 * ATT, G, nullptr,
                                           EKEEP, ATT, 512, ATT, ATT, ATT,
                                           0, 0, 0, 0, 1.f, 1, P1, P3);
    gemm<false, false, false, true, true>(feat + 512, Wvo + (long long)512 * ATT, FVo, bvo,
                                          EKEEP, ATT, 512, ATT, ATT, ATT,
                                          0, 0, 0, 0, 1.f, 1, Q1, Q3);

    // ---- attention ----
    k_rowdot<<<EKEEP, 256>>>();                             // rv = feat @ rvec
    gemm<true, false, false, true>(G, feat, S, rv,
                                   EU, EU, ATT, ATT, ATT, EU,
                                   (long long)EU * ATT, (long long)EU * ATT,
                                   (long long)EU * EU, EU, 1.f, BGR);
    k_softmax<<<EKEEP, 256>>>();
    gemm<false, true, false, false>(S, FVo, feat, nullptr,
                                    EU, ATT, EU, EU, ATT, ATT,
                                    (long long)EU * EU, (long long)EU * ATT,
                                    (long long)EU * ATT, 0, 1.f, BGR);

    // ---- LN + head + pairing ----
    k_ln_head<<<EKEEP, 256>>>(lng, lnb, hW, hb);
    k_final<<<(BGR * 128) / 256, 256>>>(ea, (float*)d_out);
}

// round 11
// speedup vs baseline: 1.6445x; 1.0595x over previous
#include <cuda_runtime.h>
#include <math.h>
#include <stdint.h>

// ---------------- problem constants ----------------
#define NTOT  8192
#define BGR   128
#define NPER  64
#define EDIR  65536
#define EKEEP 32768
#define EU    256
#define FIN   5
#define H1D   256
#define H2D   512
#define ATT   1536
#define EPSV  1e-5f

// ---------------- scratch (device globals; no allocation allowed) ----------------
__device__ float g_w[EDIR];
__device__ float g_agg1[NTOT * FIN];
__device__ float g_h1[NTOT * H1D];
__device__ float g_agg2[NTOT * H1D];
__device__ float g_h2[NTOT * H2D];
__device__ int   g_esrc[EKEEP];
__device__ int   g_edst[EKEEP];
__device__ int   g_kidx[EKEEP];
__device__ float g_feat[(size_t)EKEEP * ATT];
__device__ float g_Wq[ATT * ATT];
__device__ float g_Wk[ATT * ATT];
__device__ float g_Wv[ATT * ATT];
__device__ float g_Wqk[ATT * ATT];
__device__ float g_Wvo[ATT * ATT];
__device__ uint32_t g_WqkB[ATT * ATT];
__device__ uint32_t g_WqkS[ATT * ATT];
__device__ uint32_t g_WvoB[ATT * ATT];
__device__ uint32_t g_WvoS[ATT * ATT];
__device__ float g_bq[ATT];
__device__ float g_bv[ATT];
__device__ float g_rvec[ATT];
__device__ float g_bvo[ATT];
__device__ float g_G[(size_t)EKEEP * ATT];
__device__ float g_FVo[(size_t)EKEEP * ATT];
__device__ float g_P[2 * (size_t)NTOT * ATT];
__device__ float g_Q[2 * (size_t)NTOT * ATT];
__device__ float g_S[(size_t)BGR * EU * EU];
__device__ float g_logits[EKEEP];

// ---------------- tf32 helpers ----------------
__device__ __forceinline__ uint32_t f2tf(float x) {
    uint32_t r;
    asm("cvt.rna.tf32.f32 %0, %1;" : "=r"(r) : "f"(x));
    return r;
}
__device__ __forceinline__ void tfsplit(float x, uint32_t& b, uint32_t& s) {
    b = f2tf(x);
    s = f2tf(x - __uint_as_float(b));
}
__device__ __forceinline__ void cp16(void* smem_dst, const void* gsrc) {
    uint32_t s = (uint32_t)__cvta_generic_to_shared(smem_dst);
    asm volatile("cp.async.ca.shared.global [%0], [%1], 16;\n" :: "r"(s), "l"(gsrc));
}
#define CP_COMMIT() asm volatile("cp.async.commit_group;\n" ::: "memory")
#define CP_WAITG1() asm volatile("cp.async.wait_group 1;\n" ::: "memory")

// ---------------- 3xTF32 tensor-core GEMM: 128x128x16 tiles ----------------
// 3-stage cp.async ring, one __syncthreads per K-chunk (round-10 proven).
// PSB: B pre-split in gmem as big/small tf32 uint32 arrays -> zero B-side CVTs.
// GAT: C[row] += T1[g_esrc[row]*ATT + col] + T2[g_edst[row]*ATT + col] (bz==0 use).
template<bool TB, bool ACC, bool RELU, bool HASB, bool GAT, bool PSB>
__global__ __launch_bounds__(256) void tgemm(
    const float* __restrict__ A, const float* __restrict__ B,
    const uint32_t* __restrict__ Bsm,
    float* __restrict__ C, const float* __restrict__ bias,
    int M, int N, int K, int lda, int ldb, int ldc,
    long long sA, long long sB, long long sC, long long sBias, float alpha,
    const float* __restrict__ T1, const float* __restrict__ T2)
{
    constexpr int ASZ = 128 * 20;
    constexpr int BSZ = TB ? (128 * 20) : (16 * 136);
    extern __shared__ uint32_t smu[];
    float*    Afp = (float*)smu;
    uint32_t* Bb0 = smu + 3 * ASZ;
    uint32_t* Bb1 = smu + 3 * ASZ + 3 * BSZ;

    const int t  = threadIdx.x;
    const int bx = blockIdx.x, by = blockIdx.y, bz = blockIdx.z;
    const int n0 = bx * 128;
    const float* Ab = A + (long long)bz * sA + (long long)(by * 128) * lda;
    const float* Bb = B + (long long)bz * sB;
    const uint32_t* Bs2 = PSB ? (Bsm + (long long)bz * sB) : nullptr;
    float* Cb = C + (long long)bz * sC + (long long)(by * 128) * ldc + n0;

    const int lane = t & 31, wid = t >> 5;
    const int grp = lane >> 2, qid = lane & 3;
    const int wm = (wid & 1) * 64;
    const int wn = (wid >> 1) * 32;

    float acc[4][4][4];
#pragma unroll
    for (int mi = 0; mi < 4; mi++)
#pragma unroll
        for (int nj = 0; nj < 4; nj++)
#pragma unroll
            for (int h = 0; h < 4; h++) acc[mi][nj][h] = 0.f;

    const int ar = t >> 2, ac = (t & 3) * 4;
    const int br = t >> 5, bc = (t & 31) * 4;
    const int tr = t >> 1, tk = (t & 1) * 8;

    auto copy_tile = [&](int st, int k0) {
        float* As = Afp + st * ASZ;
        cp16(&As[ar * 20 + ac],        Ab + (long long)ar * lda + k0 + ac);
        cp16(&As[(ar + 64) * 20 + ac], Ab + (long long)(ar + 64) * lda + k0 + ac);
        uint32_t* BsB = Bb0 + st * BSZ;
        const uint32_t* srcB = (const uint32_t*)Bb;
        if (TB) {
            cp16(&BsB[tr * 20 + tk],     srcB + (long long)(n0 + tr) * ldb + k0 + tk);
            cp16(&BsB[tr * 20 + tk + 4], srcB + (long long)(n0 + tr) * ldb + k0 + tk + 4);
            if (PSB) {
                uint32_t* BsS = Bb1 + st * BSZ;
                cp16(&BsS[tr * 20 + tk],     Bs2 + (long long)(n0 + tr) * ldb + k0 + tk);
                cp16(&BsS[tr * 20 + tk + 4], Bs2 + (long long)(n0 + tr) * ldb + k0 + tk + 4);
            }
        } else {
            cp16(&BsB[br * 136 + bc],       srcB + (long long)(k0 + br) * ldb + n0 + bc);
            cp16(&BsB[(br + 8) * 136 + bc], srcB + (long long)(k0 + br + 8) * ldb + n0 + bc);
            if (PSB) {
                uint32_t* BsS = Bb1 + st * BSZ;
                cp16(&BsS[br * 136 + bc],       Bs2 + (long long)(k0 + br) * ldb + n0 + bc);
                cp16(&BsS[(br + 8) * 136 + bc], Bs2 + (long long)(k0 + br + 8) * ldb + n0 + bc);
            }
        }
    };

    auto compute = [&](int st) {
        const float* A_s = Afp + st * ASZ;
        const uint32_t* B_sB = Bb0 + st * BSZ;
        const uint32_t* B_sS = Bb1 + st * BSZ;
#pragma unroll
        for (int ks = 0; ks < 2; ks++) {
            const int k0 = ks * 8;
            uint32_t aB[4][4], aS[4][4];
#pragma unroll
            for (int mi = 0; mi < 4; mi++) {
                int r0 = wm + mi * 16 + grp;
                float f0 = A_s[r0 * 20 + k0 + qid];
                float f1 = A_s[(r0 + 8) * 20 + k0 + qid];
                float f2 = A_s[r0 * 20 + k0 + qid + 4];
                float f3 = A_s[(r0 + 8) * 20 + k0 + qid + 4];
                tfsplit(f0, aB[mi][0], aS[mi][0]);
                tfsplit(f1, aB[mi][1], aS[mi][1]);
                tfsplit(f2, aB[mi][2], aS[mi][2]);
                tfsplit(f3, aB[mi][3], aS[mi][3]);
            }
#pragma unroll
            for (int nj = 0; nj < 4; nj++) {
                int c0 = wn + nj * 8 + grp;
                const int i0 = TB ? (c0 * 20 + k0 + qid)     : ((k0 + qid) * 136 + c0);
                const int i1 = TB ? (c0 * 20 + k0 + qid + 4) : ((k0 + qid + 4) * 136 + c0);
                uint32_t b0B, b0S, b1B, b1S;
                if (PSB) {
                    b0B = B_sB[i0]; b1B = B_sB[i1];
                    b0S = B_sS[i0]; b1S = B_sS[i1];
                } else {
                    float bf0 = __uint_as_float(B_sB[i0]);
                    float bf1 = __uint_as_float(B_sB[i1]);
                    tfsplit(bf0, b0B, b0S);
                    tfsplit(bf1, b1B, b1S);
                }
#pragma unroll
                for (int mi = 0; mi < 4; mi++) {
                    asm volatile(
                        "mma.sync.aligned.m16n8k8.row.col.f32.tf32.tf32.f32 "
                        "{%0,%1,%2,%3},{%4,%5,%6,%7},{%8,%9},{%0,%1,%2,%3};"
                        : "+f"(acc[mi][nj][0]), "+f"(acc[mi][nj][1]),
                          "+f"(acc[mi][nj][2]), "+f"(acc[mi][nj][3])
                        : "r"(aB[mi][0]), "r"(aB[mi][1]), "r"(aB[mi][2]), "r"(aB[mi][3]),
                          "r"(b0S), "r"(b1S));
                    asm volatile(
                        "mma.sync.aligned.m16n8k8.row.col.f32.tf32.tf32.f32 "
                        "{%0,%1,%2,%3},{%4,%5,%6,%7},{%8,%9},{%0,%1,%2,%3};"
                        : "+f"(acc[mi][nj][0]), "+f"(acc[mi][nj][1]),
                          "+f"(acc[mi][nj][2]), "+f"(acc[mi][nj][3])
                        : "r"(aS[mi][0]), "r"(aS[mi][1]), "r"(aS[mi][2]), "r"(aS[mi][3]),
                          "r"(b0B), "r"(b1B));
                    asm volatile(
                        "mma.sync.aligned.m16n8k8.row.col.f32.tf32.tf32.f32 "
                        "{%0,%1,%2,%3},{%4,%5,%6,%7},{%8,%9},{%0,%1,%2,%3};"
                        : "+f"(acc[mi][nj][0]), "+f"(acc[mi][nj][1]),
                          "+f"(acc[mi][nj][2]), "+f"(acc[mi][nj][3])
                        : "r"(aB[mi][0]), "r"(aB[mi][1]), "r"(aB[mi][2]), "r"(aB[mi][3]),
                          "r"(b0B), "r"(b1B));
                }
            }
        }
    };

    const int nk = K / 16;
    copy_tile(0, 0);    CP_COMMIT();
    copy_tile(1, 16);   CP_COMMIT();

    for (int kc = 0; kc < nk; kc += 3) {
#pragma unroll
        for (int j = 0; j < 3; j++) {
            const int chunk = kc + j;
            if (chunk < nk) {
                CP_WAITG1();
                __syncthreads();
                compute(j);
                if (chunk + 2 < nk)
                    copy_tile((j + 2) % 3, (chunk + 2) * 16);
                CP_COMMIT();
            }
        }
    }

#pragma unroll
    for (int mi = 0; mi < 4; mi++) {
#pragma unroll
        for (int nj = 0; nj < 4; nj++) {
            int row = wm + mi * 16 + grp;
            int col = wn + nj * 8 + qid * 2;
#pragma unroll
            for (int h = 0; h < 2; h++) {
                int r = row + h * 8;
                float v0 = acc[mi][nj][h * 2 + 0] * alpha;
                float v1 = acc[mi][nj][h * 2 + 1] * alpha;
                if (HASB) {
                    const float* bp = bias + (long long)bz * sBias + n0 + col;
                    v0 += bp[0]; v1 += bp[1];
                }
                if (GAT) {
                    int e = by * 128 + r;
                    int es = g_esrc[e], ed = g_edst[e];
                    float2 t1 = *reinterpret_cast<const float2*>(&T1[(long long)es * ATT + n0 + col]);
                    float2 t2 = *reinterpret_cast<const float2*>(&T2[(long long)ed * ATT + n0 + col]);
                    v0 += t1.x + t2.x; v1 += t1.y + t2.y;
                }
                float2* cp = reinterpret_cast<float2*>(Cb + (long long)r * ldc + col);
                if (ACC) { float2 c = *cp; v0 += c.x; v1 += c.y; }
                if (RELU) { v0 = fmaxf(v0, 0.f); v1 = fmaxf(v1, 0.f); }
                *cp = make_float2(v0, v1);
            }
        }
    }
}

// ---------------- small kernels ----------------
__global__ void k_zero(float* p, int n) {
    int i = blockIdx.x * 256 + threadIdx.x;
    if (i < n) p[i] = 0.f;
}

__global__ void k_split(const float* __restrict__ src, uint32_t* __restrict__ dB,
                        uint32_t* __restrict__ dS, int n) {
    int i = blockIdx.x * 256 + threadIdx.x;
    if (i < n) {
        uint32_t b, s;
        tfsplit(src[i], b, s);
        dB[i] = b; dS[i] = s;
    }
}

__global__ void k_edgew(const float* __restrict__ ea, const float* __restrict__ W,
                        const float* __restrict__ b) {
    int e = blockIdx.x * 256 + threadIdx.x;
    if (e < EDIR) {
        float a = ea[2 * e], c = ea[2 * e + 1];
        float v = a * W[0] + ((c < 0.5f) ? W[1] : W[2]) + b[0];
        g_w[e] = fmaxf(v, 0.f);
    }
}

__global__ void k_sc1(const int* __restrict__ edges, const float* __restrict__ x) {
    int e = blockIdx.x * 256 + threadIdx.x;
    if (e < EDIR) {
        int s = edges[e], d = edges[EDIR + e];
        float wv = g_w[e];
        if (wv != 0.f) {
#pragma unroll
            for (int f = 0; f < FIN; f++)
                atomicAdd(&g_agg1[d * FIN + f], wv * x[s * FIN + f]);
        }
    }
}

__global__ void k_gc1(const float* __restrict__ x, const float* __restrict__ Wrel,
                      const float* __restrict__ brel, const float* __restrict__ Wroot) {
    int idx = blockIdx.x * 256 + threadIdx.x;
    int n = idx >> 8, j = idx & 255;
    float s = brel[j];
#pragma unroll
    for (int f = 0; f < FIN; f++) {
        s += g_agg1[n * FIN + f] * Wrel[f * H1D + j];
        s += x[n * FIN + f] * Wroot[f * H1D + j];
    }
    g_h1[idx] = fmaxf(s, 0.f);
}

__global__ void k_sc2(const int* __restrict__ edges) {
    int e = blockIdx.x;
    int t = threadIdx.x;
    int s = edges[e], d = edges[EDIR + e];
    float wv = g_w[e];
    if (wv == 0.f) return;
    float4 hv = *reinterpret_cast<const float4*>(&g_h1[s * H1D + t * 4]);
    atomicAdd(&g_agg2[d * H1D + t * 4 + 0], wv * hv.x);
    atomicAdd(&g_agg2[d * H1D + t * 4 + 1], wv * hv.y);
    atomicAdd(&g_agg2[d * H1D + t * 4 + 2], wv * hv.z);
    atomicAdd(&g_agg2[d * H1D + t * 4 + 3], wv * hv.w);
}

__global__ void k_gnorm(const float* __restrict__ gw, const float* __restrict__ gb,
                        const float* __restrict__ gms) {
    int g = blockIdx.x, j = threadIdx.x;
    float s = 0.f;
    for (int n = 0; n < NPER; n++) s += g_h2[((g << 6) + n) * H2D + j];
    float mean = s * (1.f / NPER);
    float ms = gms[j];
    float off = ms * mean;
    float s2 = 0.f;
    for (int n = 0; n < NPER; n++) {
        float c = g_h2[((g << 6) + n) * H2D + j] - off;
        s2 += c * c;
    }
    float inv = rsqrtf(s2 * (1.f / NPER) + EPSV);
    float wv = gw[j], bv = gb[j];
    for (int n = 0; n < NPER; n++) {
        int idx = ((g << 6) + n) * H2D + j;
        g_h2[idx] = wv * (g_h2[idx] - off) * inv + bv;
    }
}

__global__ void k_sort(const int* __restrict__ edges) {
    __shared__ unsigned int key[256];
    int g = blockIdx.x, t = threadIdx.x;
    int ge = g * 512 + 256 + t;
    int s = edges[ge], d = edges[EDIR + ge];
    unsigned int k = ((unsigned)((s - (g << 6)) * 64 + (d - (g << 6))) << 8) | (unsigned)t;
    key[t] = k;
    __syncthreads();
    for (int kk = 2; kk <= 256; kk <<= 1) {
        for (int j = kk >> 1; j > 0; j >>= 1) {
            int ixj = t ^ j;
            if (ixj > t) {
                unsigned a = key[t], b = key[ixj];
                bool up = (t & kk) == 0;
                if ((a > b) == up) { key[t] = b; key[ixj] = a; }
            }
            __syncthreads();
        }
    }
    int slot = key[t] & 255;
    int ge2 = g * 512 + 256 + slot;
    int i = g * 256 + t;
    g_esrc[i] = edges[ge2];
    g_edst[i] = edges[EDIR + ge2];
    g_kidx[i] = ge2;
}

__global__ void k_feat(const float* __restrict__ ea, const float* __restrict__ eW,
                       const float* __restrict__ eb) {
    int i = blockIdx.x, t = threadIdx.x;
    int s = g_esrc[i], d = g_edst[i], ke = g_kidx[i];
    float a = ea[2 * ke], c = ea[2 * ke + 1];
    float* F = g_feat + (long long)i * ATT;
    for (int j = t; j < H2D; j += 256) {
        F[j]        = g_h2[s * H2D + j];
        F[1024 + j] = g_h2[d * H2D + j];
        float e = a * eW[j] + ((c < 0.5f) ? eW[512 + j] : eW[1024 + j]) + eb[j];
        F[512 + j] = fmaxf(e, 0.f);
    }
}

__global__ void k_vecmat(const float* __restrict__ x, const float* __restrict__ W,
                         const float* __restrict__ b, float* __restrict__ y,
                         int K, int N, int ldw) {
    int j = blockIdx.x * 256 + threadIdx.x;
    if (j < N) {
        float s = b ? b[j] : 0.f;
        for (int i = 0; i < K; i++) s += x[i] * W[(long long)i * ldw + j];
        y[j] = s;
    }
}

__global__ void k_matvecr(const float* __restrict__ W, const float* __restrict__ x,
                          float* __restrict__ y, float scale) {
    int row = blockIdx.x, t = threadIdx.x;
    float s = 0.f;
    for (int j = t; j < ATT; j += 256) s += W[(long long)row * ATT + j] * x[j];
    __shared__ float red[256];
    red[t] = s; __syncthreads();
    for (int st = 128; st > 0; st >>= 1) { if (t < st) red[t] += red[t + st]; __syncthreads(); }
    if (t == 0) y[row] = red[0] * scale;
}

__global__ void k_softmax() {
    int rb = blockIdx.x, t = threadIdx.x;
    float v = g_S[(long long)rb * 256 + t];
    __shared__ float red[256];
    red[t] = v; __syncthreads();
    for (int s = 128; s > 0; s >>= 1) { if (t < s) red[t] = fmaxf(red[t], red[t + s]); __syncthreads(); }
    float m = red[0]; __syncthreads();
    float e = __expf(v - m);
    red[t] = e; __syncthreads();
    for (int s = 128; s > 0; s >>= 1) { if (t < s) red[t] += red[t + s]; __syncthreads(); }
    g_S[(long long)rb * 256 + t] = e / red[0];
}

__global__ void k_ln_head(const float* __restrict__ lng, const float* __restrict__ lnb,
                          const float* __restrict__ hW, const float* __restrict__ hb) {
    int row = blockIdx.x, t = threadIdx.x;
    const float* x = g_feat + (long long)row * ATT;
    float loc[6];
    float s = 0.f;
#pragma unroll
    for (int i = 0; i < 6; i++) { loc[i] = x[t + i * 256]; s += loc[i]; }
    __shared__ float red[256];
    red[t] = s; __syncthreads();
    for (int st = 128; st > 0; st >>= 1) { if (t < st) red[t] += red[t + st]; __syncthreads(); }
    float mu = red[0] * (1.f / ATT); __syncthreads();
    float s2 = 0.f;
#pragma unroll
    for (int i = 0; i < 6; i++) { float d = loc[i] - mu; s2 += d * d; }
    red[t] = s2; __syncthreads();
    for (int st = 128; st > 0; st >>= 1) { if (t < st) red[t] += red[t + st]; __syncthreads(); }
    float inv = rsqrtf(red[0] * (1.f / ATT) + EPSV); __syncthreads();
    float o = 0.f;
#pragma unroll
    for (int i = 0; i < 6; i++) {
        int j = t + i * 256;
        float nv = lng[j] * (loc[i] - mu) * inv + lnb[j];
        o += nv * hW[j];
    }
    red[t] = o; __syncthreads();
    for (int st = 128; st > 0; st >>= 1) { if (t < st) red[t] += red[t + st]; __syncthreads(); }
    if (t == 0) g_logits[row] = red[0] + hb[0];
}

__global__ void k_final(const float* __restrict__ ea, float* __restrict__ out) {
    int idx = blockIdx.x * 256 + threadIdx.x;
    if (idx < BGR * 128) {
        int i0 = 2 * idx, i1 = i0 + 1;
        float v0 = g_logits[i0], v1 = g_logits[i1];
        float c0 = ea[2 * g_kidx[i0] + 1], c1 = ea[2 * g_kidx[i1] + 1];
        int m = (v1 < v0) ? 1 : 0;
        out[idx * 2 + 0] = (float)g_esrc[i0];
        out[idx * 2 + 1] = (float)g_edst[i0];
        out[32768 + idx] = m ? v1 : v0;
        out[49152 + idx] = m ? c1 : c0;
    }
}

// ---------------- host-side GEMM dispatch ----------------
template<bool TB, bool ACC, bool RELU, bool HASB, bool GAT = false, bool PSB = false>
static void gemm(const float* A, const float* B, float* C, const float* bias,
                 int M, int N, int K, int lda, int ldb, int ldc,
                 long long sA, long long sB, long long sC, long long sBias,
                 float alpha, int batch,
                 const float* T1 = nullptr, const float* T2 = nullptr,
                 const uint32_t* Bsm = nullptr) {
    constexpr int ASZ = 128 * 20;
    constexpr int BSZ = TB ? (128 * 20) : (16 * 136);
    constexpr int SMEM = (3 * ASZ + (PSB ? 6 : 3) * BSZ) * 4;
    cudaFuncSetAttribute(tgemm<TB, ACC, RELU, HASB, GAT, PSB>,
                         cudaFuncAttributeMaxDynamicSharedMemorySize, SMEM);
    dim3 grid(N / 128, M / 128, batch);
    tgemm<TB, ACC, RELU, HASB, GAT, PSB><<<grid, 256, SMEM>>>(
        A, B, Bsm, C, bias, M, N, K, lda, ldb, ldc, sA, sB, sC, sBias, alpha, T1, T2);
}

static float* sym(const void* s) {
    void* p = nullptr;
    cudaGetSymbolAddress(&p, s);
    return (float*)p;
}

extern "C" void kernel_launch(void* const* d_in, const int* in_sizes, int n_in,
                              void* d_out, int out_size) {
    const float* x       = (const float*)d_in[0];
    const int*   edges   = (const int*)d_in[1];
    const float* ea      = (const float*)d_in[2];
    const float* wembW   = (const float*)d_in[5];
    const float* wembB   = (const float*)d_in[6];
    const float* gc1Wrel = (const float*)d_in[7];
    const float* gc1brel = (const float*)d_in[8];
    const float* gc1Wroot= (const float*)d_in[9];
    const float* gc2Wrel = (const float*)d_in[10];
    const float* gc2brel = (const float*)d_in[11];
    const float* gc2Wroot= (const float*)d_in[12];
    const float* gnw     = (const float*)d_in[13];
    const float* gnb     = (const float*)d_in[14];
    const float* gnms    = (const float*)d_in[15];
    const float* eW      = (const float*)d_in[16];
    const float* ebias   = (const float*)d_in[17];
    const float* qkvW    = (const float*)d_in[18];
    const float* qkvb    = (const float*)d_in[19];
    const float* inWq    = (const float*)d_in[20];
    const float* inWk    = (const float*)d_in[21];
    const float* inWv    = (const float*)d_in[22];
    const float* inbq    = (const float*)d_in[23];
    const float* inbv    = (const float*)d_in[25];
    const float* outW    = (const float*)d_in[26];
    const float* outb    = (const float*)d_in[27];
    const float* lng     = (const float*)d_in[28];
    const float* lnb     = (const float*)d_in[29];
    const float* hW      = (const float*)d_in[30];
    const float* hb      = (const float*)d_in[31];
    (void)in_sizes; (void)n_in; (void)out_size;

    float* agg1 = sym(g_agg1);  float* agg2 = sym(g_agg2);
    float* h1   = sym(g_h1);    float* h2   = sym(g_h2);
    float* feat = sym(g_feat);
    float* Wq   = sym(g_Wq);    float* Wk  = sym(g_Wk);   float* Wv  = sym(g_Wv);
    float* Wqk  = sym(g_Wqk);   float* Wvo = sym(g_Wvo);
    uint32_t* WqkB = (uint32_t*)sym(g_WqkB);
    uint32_t* WqkS = (uint32_t*)sym(g_WqkS);
    uint32_t* WvoB = (uint32_t*)sym(g_WvoB);
    uint32_t* WvoS = (uint32_t*)sym(g_WvoS);
    float* bq   = sym(g_bq);    float* bv  = sym(g_bv);
    float* rvec = sym(g_rvec);  float* bvo = sym(g_bvo);
    float* G    = sym(g_G);     float* FVo = sym(g_FVo);  float* S   = sym(g_S);
    float* P    = sym(g_P);     float* Q   = sym(g_Q);

    float* P1 = P;  float* P3 = P + (long long)NTOT * ATT;
    float* Q1 = Q;  float* Q3 = Q + (long long)NTOT * ATT;

    const float scale = 1.0f / sqrtf((float)ATT);
    const int ATTSQ = ATT * ATT;

    // ---- weight folds first; launch index 3 = Wqk fold (ncu profiles index 3) ----
    gemm<false, false, false, false>(qkvW + 0,    inWq, Wq, nullptr, ATT, ATT, ATT, 3 * ATT, ATT, ATT, 0, 0, 0, 0, 1.f, 1);
    gemm<false, false, false, false>(qkvW + ATT,  inWk, Wk, nullptr, ATT, ATT, ATT, 3 * ATT, ATT, ATT, 0, 0, 0, 0, 1.f, 1);
    gemm<false, false, false, false>(qkvW + 2*ATT,inWv, Wv, nullptr, ATT, ATT, ATT, 3 * ATT, ATT, ATT, 0, 0, 0, 0, 1.f, 1);
    gemm<true,  false, false, false>(Wq, Wk, Wqk, nullptr, ATT, ATT, ATT, ATT, ATT, ATT, 0, 0, 0, 0, scale, 1);   // PROFILED
    gemm<false, false, false, false>(Wv, outW, Wvo, nullptr, ATT, ATT, ATT, ATT, ATT, ATT, 0, 0, 0, 0, 1.f, 1);
    k_split<<<(ATTSQ + 255) / 256, 256>>>(Wqk, WqkB, WqkS, ATTSQ);
    k_split<<<(ATTSQ + 255) / 256, 256>>>(Wvo, WvoB, WvoS, ATTSQ);
    k_vecmat<<<ATT / 256, 256>>>(qkvb + 0,     inWq, inbq, bq, ATT, ATT, ATT);
    k_vecmat<<<ATT / 256, 256>>>(qkvb + 2*ATT, inWv, inbv, bv, ATT, ATT, ATT);
    k_matvecr<<<ATT, 256>>>(Wk, bq, rvec, scale);           // r = scale * Wk_eff @ bq_eff
    k_vecmat<<<ATT / 256, 256>>>(bv, outW, outb, bvo, ATT, ATT, ATT);

    // ---- GNN front-end ----
    k_zero<<<(NTOT * FIN + 255) / 256, 256>>>(agg1, NTOT * FIN);
    k_zero<<<(NTOT * H1D + 255) / 256, 256>>>(agg2, NTOT * H1D);
    k_edgew<<<EDIR / 256, 256>>>(ea, wembW, wembB);
    k_sc1<<<EDIR / 256, 256>>>(edges, x);
    k_gc1<<<NTOT * H1D / 256, 256>>>(x, gc1Wrel, gc1brel, gc1Wroot);
    k_sc2<<<EDIR, 64>>>(edges);
    gemm<false, false, false, false>(agg2, gc2Wrel, h2, nullptr,
                                     NTOT, H2D, H1D, H1D, H2D, H2D, 0, 0, 0, 0, 1.f, 1);
    gemm<false, true, true, true>(h1, gc2Wroot, h2, gc2brel,
                                  NTOT, H2D, H1D, H1D, H2D, H2D, 0, 0, 0, 0, 1.f, 1);
    k_gnorm<<<BGR, H2D>>>(gnw, gnb, gnms);

    // ---- edge selection + sort + feature assembly ----
    k_sort<<<BGR, 256>>>(edges);
    k_feat<<<EKEEP, 256>>>(ea, eW, ebias);

    // ---- decomposed projections (pre-split B) ----
    // [P1|P3] = h2 @ {Wqk_top, Wqk_bot}   (z=2, B = pre-split big/small)
    gemm<false, false, false, false, false, true>(
        h2, (const float*)WqkB, P, nullptr, NTOT, ATT, 512, H2D, ATT, ATT,
        0, (long long)1024 * ATT, (long long)NTOT * ATT, 0, 1.f, 2,
        nullptr, nullptr, WqkS);
    // [Q1|Q3] = h2 @ {Wvo_top, Wvo_bot}
    gemm<false, false, false, false, false, true>(
        h2, (const float*)WvoB, Q, nullptr, NTOT, ATT, 512, H2D, ATT, ATT,
        0, (long long)1024 * ATT, (long long)NTOT * ATT, 0, 1.f, 2,
        nullptr, nullptr, WvoS);
    // G = emb @ Wqk_mid + P1[src] + P3[dst] + rvec   (rvec bias folds scores' rv)
    gemm<false, false, false, true, true, true>(
        feat + 512, (const float*)(WqkB + (long long)512 * ATT), G, rvec,
        EKEEP, ATT, 512, ATT, ATT, ATT, 0, 0, 0, 0, 1.f, 1,
        P1, P3, WqkS + (long long)512 * ATT);
    // FVo = emb @ Wvo_mid + Q1[src] + Q3[dst] + bvo
    gemm<false, false, false, true, true, true>(
        feat + 512, (const float*)(WvoB + (long long)512 * ATT), FVo, bvo,
        EKEEP, ATT, 512, ATT, ATT, ATT, 0, 0, 0, 0, 1.f, 1,
        Q1, Q3, WvoS + (long long)512 * ATT);

    // ---- attention ----
    gemm<true, false, false, false>(G, feat, S, nullptr,
                                    EU, EU, ATT, ATT, ATT, EU,
                                    (long long)EU * ATT, (long long)EU * ATT,
                                    (long long)EU * EU, 0, 1.f, BGR);
    k_softmax<<<EKEEP, 256>>>();
    gemm<false, true, false, false>(S, FVo, feat, nullptr,
                                    EU, ATT, EU, EU, ATT, ATT,
                                    (long long)EU * EU, (long long)EU * ATT,
                                    (long long)EU * ATT, 0, 1.f, BGR);

    // ---- LN + head + pairing ----
    k_ln_head<<<EKEEP, 256>>>(lng, lnb, hW, hb);
    k_final<<<(BGR * 128) / 256, 256>>>(ea, (float*)d_out);
}